// round 9
// baseline (speedup 1.0000x reference)
#include <cuda_runtime.h>
#include <math.h>
#include <stdint.h>

#define B_   256
#define T_   64
#define H_   1024
#define V_   128
#define L_   32
#define N4H  4096

// ---- GEMM tiling: CTA 128x64, 8 warps (warp 32x32), chunks of K=32 ----
#define NCH  32              // total chunks over K=1024
#define ACH  4096
#define BCH  2048
#define NSTAGE 2
#define STG_FLOATS (2*ACH + 2*BCH)             // 12288
#define SMEM_BYTES (NSTAGE * STG_FLOATS * 4)   // 98304 -> 2 CTAs/SM

// ---------------- persistent device scratch ----------------
__device__ float g_h[B_ * H_];
__device__ float g_c[B_ * H_];
__device__ float g_z[2 * B_ * N4H];            // two split-K partial buffers
__device__ int   g_tok[B_];
__device__ float g_AH[B_ * H_];
__device__ float g_AL[B_ * H_];
__device__ float g_EH[V_ * H_];
__device__ float g_EL[V_ * H_];
__device__ float g_BeH[(size_t)N4H * H_];
__device__ float g_BeL[(size_t)N4H * H_];
__device__ float g_BdH[(size_t)N4H * H_];
__device__ float g_BdL[(size_t)N4H * H_];
__device__ float g_BwH[(size_t)N4H * H_];
__device__ float g_BwL[(size_t)N4H * H_];
__device__ float g_encEW[V_ * N4H];
__device__ float g_decEW[V_ * N4H];

// ---------------- helpers ----------------
__device__ __forceinline__ void split_tf32(float x, float& hi, float& lo) {
    uint32_t u;
    asm("cvt.rna.tf32.f32 %0, %1;" : "=r"(u) : "f"(x));
    hi = __uint_as_float(u);
    uint32_t u2;
    float r = x - hi;
    asm("cvt.rna.tf32.f32 %0, %1;" : "=r"(u2) : "f"(r));
    lo = __uint_as_float(u2);
}

__device__ __forceinline__ void mma_tf32(float* d, const float* a, const float* b) {
    asm volatile(
        "mma.sync.aligned.m16n8k8.row.col.f32.tf32.tf32.f32 "
        "{%0,%1,%2,%3}, {%4,%5,%6,%7}, {%8,%9}, {%0,%1,%2,%3};"
        : "+f"(d[0]), "+f"(d[1]), "+f"(d[2]), "+f"(d[3])
        : "r"(__float_as_uint(a[0])), "r"(__float_as_uint(a[1])),
          "r"(__float_as_uint(a[2])), "r"(__float_as_uint(a[3])),
          "r"(__float_as_uint(b[0])), "r"(__float_as_uint(b[1])));
}

__device__ __forceinline__ void cpa16(uint32_t dst, const float* src) {
    asm volatile("cp.async.cg.shared.global [%0], [%1], 16;" :: "r"(dst), "l"(src) : "memory");
}
__device__ __forceinline__ void cpa_commit() {
    asm volatile("cp.async.commit_group;" ::: "memory");
}
template<int N> __device__ __forceinline__ void cpa_wait() {
    asm volatile("cp.async.wait_group %0;" :: "n"(N) : "memory");
}

// Write one (m, m+8) x (j0..j0+7) group into the A blob (split on the fly).
__device__ __forceinline__ void write_Ablob(float* AH, float* AL, int m, int j0,
                                            const float* r0, const float* r1)
{
    int tile = m >> 7, chunk = j0 >> 5, wm_g = (m & 127) >> 5, k8 = (j0 & 31) >> 3;
    int mf = (m & 31) >> 4, gid = m & 7;
    size_t base = ((size_t)tile * NCH + chunk) * ACH + (size_t)(((wm_g * 4 + k8) * 2 + mf) * 128 + gid * 16);
#pragma unroll
    for (int tig = 0; tig < 4; tig++) {
        float4 h4, l4;
        split_tf32(r0[tig],     h4.x, l4.x);
        split_tf32(r1[tig],     h4.y, l4.y);
        split_tf32(r0[4 + tig], h4.z, l4.z);
        split_tf32(r1[4 + tig], h4.w, l4.w);
        *(float4*)(AH + base + tig * 4) = h4;
        *(float4*)(AL + base + tig * 4) = l4;
    }
}

// ---------------- weight split: W[1024][4096] -> mma-ready B blob ----------------
__global__ void split_weightB(const float* __restrict__ W,
                              float* __restrict__ BH, float* __restrict__ BL)
{
    __shared__ float sH[32][33];
    __shared__ float sL[32][33];
    int n0 = blockIdx.x * 32, k0 = blockIdx.y * 32;
    int tx = threadIdx.x & 31, ty = threadIdx.x >> 5;
#pragma unroll
    for (int i = 0; i < 4; i++) {
        int k = ty + i * 8;
        float x = W[(size_t)(k0 + k) * N4H + n0 + tx];
        float hi, lo;
        split_tf32(x, hi, lo);
        sH[k][tx] = hi;
        sL[k][tx] = lo;
    }
    __syncthreads();
    int tile_n = n0 >> 6, wn_g = (n0 >> 5) & 1, chunk = k0 >> 5;
    size_t obase = ((size_t)tile_n * NCH + chunk) * BCH + wn_g * 1024;
    int o4 = threadIdx.x;
    int k8 = o4 >> 6, vh = (o4 >> 5) & 1, lane = o4 & 31;
    int gid = lane >> 2, tig = lane & 3;
    int n_a = (vh * 2 + 0) * 8 + gid;
    int n_b = (vh * 2 + 1) * 8 + gid;
    int k_a = k8 * 8 + tig;
    int k_b = k8 * 8 + 4 + tig;
    float4 vH, vL;
    vH.x = sH[k_a][n_a]; vH.y = sH[k_b][n_a]; vH.z = sH[k_a][n_b]; vH.w = sH[k_b][n_b];
    vL.x = sL[k_a][n_a]; vL.y = sL[k_b][n_a]; vL.z = sL[k_a][n_b]; vL.w = sL[k_b][n_b];
    *(float4*)(BH + obase + o4 * 4) = vH;
    *(float4*)(BL + obase + o4 * 4) = vL;
}

// ---------------- emb -> A blob (128 rows, tile 0) ----------------
__global__ void emb_blob(const float* __restrict__ emb,
                         float* __restrict__ AH, float* __restrict__ AL)
{
    int t = blockIdx.x * 256 + threadIdx.x;
    if (t >= 8192) return;
    int mp = t >> 7;
    int m  = ((mp >> 3) << 4) | (mp & 7);
    int j0 = (t & 127) << 3;
    float r0[8], r1[8];
    const float* p0 = emb + (size_t)m * H_ + j0;
    const float* p1 = emb + (size_t)(m + 8) * H_ + j0;
#pragma unroll
    for (int i = 0; i < 8; i++) { r0[i] = p0[i]; r1[i] = p1[i]; }
    write_Ablob(AH, AL, m, j0, r0, r1);
}

// ---------------- tensor-core step GEMM (split-K over gridDim.z) ----------------
// blockIdx.z = k-half; half 0 applies bias+table, half 1 raw partial.
__global__ __launch_bounds__(256, 2)
void gemm_tc(const float* __restrict__ AH, const float* __restrict__ AL,
             const float* __restrict__ BH, const float* __restrict__ BL,
             const float* __restrict__ bias,
             const float* __restrict__ addTbl, const int* __restrict__ addIdx, int idxStride,
             int nchPer, int Mtot,
             float* __restrict__ Z)
{
    extern __shared__ float sm[];
    const int tid = threadIdx.x;
    const int wid = tid >> 5;
    const int lid = tid & 31;
    const int gid = lid >> 2;
    const int tig = lid & 3;
    const int bn  = blockIdx.x * 64;
    const int bm  = blockIdx.y * 128;
    const int wm_g = wid & 3;
    const int wn_g = wid >> 2;
    const int ch0 = blockIdx.z * nchPer;

    const float* AHt = AH + (size_t)blockIdx.y * NCH * ACH;
    const float* ALt = AL + (size_t)blockIdx.y * NCH * ACH;
    const float* BHt = BH + (size_t)blockIdx.x * NCH * BCH;
    const float* BLt = BL + (size_t)blockIdx.x * NCH * BCH;

    const uint32_t smb = (uint32_t)__cvta_generic_to_shared(sm);

    auto stage = [&](int s, int cc) {
        uint32_t d = smb + (uint32_t)s * (STG_FLOATS * 4);
        const float* aH = AHt + (size_t)cc * ACH;
        const float* aL = ALt + (size_t)cc * ACH;
        const float* bH = BHt + (size_t)cc * BCH;
        const float* bL = BLt + (size_t)cc * BCH;
#pragma unroll
        for (int i = 0; i < 4; i++) {
            int u = tid + i * 256;
            cpa16(d + u * 16,              aH + u * 4);
            cpa16(d + ACH * 4 + u * 16,    aL + u * 4);
        }
#pragma unroll
        for (int i = 0; i < 2; i++) {
            int u = tid + i * 256;
            cpa16(d + 2 * ACH * 4 + u * 16,             bH + u * 4);
            cpa16(d + (2 * ACH + BCH) * 4 + u * 16,     bL + u * 4);
        }
        cpa_commit();
    };

    float acc[2][4][4];
#pragma unroll
    for (int mf = 0; mf < 2; mf++)
#pragma unroll
        for (int nf = 0; nf < 4; nf++)
#pragma unroll
            for (int q = 0; q < 4; q++) acc[mf][nf][q] = 0.f;

    stage(0, ch0);
    if (nchPer > 1) stage(1, ch0 + 1);

    const int aoffB = (wm_g * 4) * 256 + lid * 4;
    const int boffB = (wn_g * 4) * 256 + lid * 4;

    float4 fa[2][4], fb[2][4];

    for (int c = 0; c < nchPer; c++) {
        const int s = c & 1;
        if (c == nchPer - 1) cpa_wait<0>(); else cpa_wait<1>();
        __syncthreads();

        const float* sAH = sm + s * STG_FLOATS;
        const float* sAL = sAH + ACH;
        const float* sBH = sAH + 2 * ACH;
        const float* sBL = sAH + 2 * ACH + BCH;

        fa[0][0] = *(const float4*)(sAH + aoffB);
        fa[0][1] = *(const float4*)(sAH + aoffB + 128);
        fa[0][2] = *(const float4*)(sAL + aoffB);
        fa[0][3] = *(const float4*)(sAL + aoffB + 128);
        fb[0][0] = *(const float4*)(sBH + boffB);
        fb[0][1] = *(const float4*)(sBH + boffB + 128);
        fb[0][2] = *(const float4*)(sBL + boffB);
        fb[0][3] = *(const float4*)(sBL + boffB + 128);

#pragma unroll
        for (int k8 = 0; k8 < 4; k8++) {
            const int cur = k8 & 1;
            const int nxt = cur ^ 1;
            if (k8 < 3) {
                int o = (k8 + 1) * 256;
                fa[nxt][0] = *(const float4*)(sAH + aoffB + o);
                fa[nxt][1] = *(const float4*)(sAH + aoffB + o + 128);
                fa[nxt][2] = *(const float4*)(sAL + aoffB + o);
                fa[nxt][3] = *(const float4*)(sAL + aoffB + o + 128);
                fb[nxt][0] = *(const float4*)(sBH + boffB + o);
                fb[nxt][1] = *(const float4*)(sBH + boffB + o + 128);
                fb[nxt][2] = *(const float4*)(sBL + boffB + o);
                fb[nxt][3] = *(const float4*)(sBL + boffB + o + 128);
            }
            const float* aH0 = (const float*)&fa[cur][0];
            const float* aH1 = (const float*)&fa[cur][1];
            const float* aL0 = (const float*)&fa[cur][2];
            const float* aL1 = (const float*)&fa[cur][3];
            float bH[4][2] = {{fb[cur][0].x, fb[cur][0].y}, {fb[cur][0].z, fb[cur][0].w},
                              {fb[cur][1].x, fb[cur][1].y}, {fb[cur][1].z, fb[cur][1].w}};
            float bL[4][2] = {{fb[cur][2].x, fb[cur][2].y}, {fb[cur][2].z, fb[cur][2].w},
                              {fb[cur][3].x, fb[cur][3].y}, {fb[cur][3].z, fb[cur][3].w}};
#pragma unroll
            for (int nf = 0; nf < 4; nf++) {
                mma_tf32(acc[0][nf], aH0, bH[nf]);
                mma_tf32(acc[1][nf], aH1, bH[nf]);
            }
#pragma unroll
            for (int nf = 0; nf < 4; nf++) {
                mma_tf32(acc[0][nf], aH0, bL[nf]);
                mma_tf32(acc[1][nf], aH1, bL[nf]);
            }
#pragma unroll
            for (int nf = 0; nf < 4; nf++) {
                mma_tf32(acc[0][nf], aL0, bH[nf]);
                mma_tf32(acc[1][nf], aL1, bH[nf]);
            }
        }
        __syncthreads();
        if (c + 2 < nchPer) stage(s, ch0 + c + 2);
    }

    // ---- epilogue ----
    const int applyExtra = (blockIdx.z == 0);
    float* Zc = Z + (size_t)blockIdx.z * Mtot * N4H;
#pragma unroll
    for (int mf = 0; mf < 2; mf++) {
#pragma unroll
        for (int half = 0; half < 2; half++) {
            int m = bm + wm_g * 32 + mf * 16 + half * 8 + gid;
            const float* arow = (applyExtra && addTbl) ? (addTbl + (size_t)addIdx[(size_t)m * idxStride] * N4H) : nullptr;
            float* zrow = Zc + (size_t)m * N4H;
#pragma unroll
            for (int nf = 0; nf < 4; nf++) {
                int cn = bn + wn_g * 32 + nf * 8 + tig * 2;
                float v0 = acc[mf][nf][half * 2 + 0];
                float v1 = acc[mf][nf][half * 2 + 1];
                if (applyExtra && bias) { v0 += bias[cn]; v1 += bias[cn + 1]; }
                if (arow) { v0 += arow[cn]; v1 += arow[cn + 1]; }
                float2 o; o.x = v0; o.y = v1;
                *(float2*)(zrow + cn) = o;
            }
        }
    }
}

// ---------------- LSTM cell: sum split-K partials + gates + masked update + blob emit ----------------
__global__ void lstm_cell(const float* __restrict__ Z, int nSplit,
                          const int* __restrict__ maskSrc, int maskStride,
                          float* __restrict__ h, float* __restrict__ c,
                          float* __restrict__ AH, float* __restrict__ AL)
{
    int t = blockIdx.x * blockDim.x + threadIdx.x;
    if (t >= 16384) return;
    int mp = t >> 7;
    int m  = ((mp >> 3) << 4) | (mp & 7);
    int j0 = (t & 127) << 3;
    const float* Z1 = Z + (size_t)B_ * N4H;

    float hv[2][8];
#pragma unroll
    for (int half = 0; half < 2; half++) {
        int mm = m + half * 8;
        bool act = maskSrc[(size_t)mm * maskStride] != 0;
        if (act) {
            const float* zr = Z + (size_t)mm * N4H + j0;
            const float* zs = Z1 + (size_t)mm * N4H + j0;
            float* cp = c + (size_t)mm * H_ + j0;
            float* hp = h + (size_t)mm * H_ + j0;
            float4 hout[2], cout[2];
#pragma unroll
            for (int q = 0; q < 8; q++) {
                float vi = zr[q];        float vf = zr[1024 + q];
                float vg = zr[2048 + q]; float vo = zr[3072 + q];
                if (nSplit == 2) {
                    vi += zs[q];        vf += zs[1024 + q];
                    vg += zs[2048 + q]; vo += zs[3072 + q];
                }
                float vc = cp[q];
                float ig = 1.0f / (1.0f + expf(-vi));
                float fg = 1.0f / (1.0f + expf(-vf));
                float gg = tanhf(vg);
                float og = 1.0f / (1.0f + expf(-vo));
                float c2 = fg * vc + ig * gg;
                float h2 = og * tanhf(c2);
                ((float*)&cout[q >> 2].x)[q & 3] = c2;
                ((float*)&hout[q >> 2].x)[q & 3] = h2;
                hv[half][q] = h2;
            }
            *(float4*)(cp)     = cout[0];
            *(float4*)(cp + 4) = cout[1];
            *(float4*)(hp)     = hout[0];
            *(float4*)(hp + 4) = hout[1];
        } else {
            const float* hp = h + (size_t)mm * H_ + j0;
#pragma unroll
            for (int q = 0; q < 8; q++) hv[half][q] = hp[q];
        }
    }
    write_Ablob(AH, AL, m, j0, hv[0], hv[1]);
}

// ---------------- decoder output: logits + softmax + argmax ----------------
__global__ void dec_output(const float* __restrict__ h,
                           const float* __restrict__ outW, const float* __restrict__ outb,
                           float* __restrict__ out, int l,
                           int* __restrict__ tok, float* __restrict__ tokOut)
{
    const int ROWS = 4;
    __shared__ float hs[ROWS][H_];
    __shared__ float red[V_];
    __shared__ float smax, ssum;
    __shared__ int   sarg;

    int m0 = blockIdx.x * ROWS;
    int v  = threadIdx.x;

    for (int idx = threadIdx.x; idx < ROWS * H_; idx += blockDim.x) {
        int r = idx >> 10;
        hs[r][idx & 1023] = h[(size_t)(m0 + r) * H_ + (idx & 1023)];
    }
    __syncthreads();

    float acc[ROWS] = {0.f, 0.f, 0.f, 0.f};
#pragma unroll 8
    for (int k = 0; k < H_; k++) {
        float w = outW[(size_t)k * V_ + v];
#pragma unroll
        for (int r = 0; r < ROWS; r++) acc[r] += hs[r][k] * w;
    }
    float bb = outb[v];

    for (int r = 0; r < ROWS; r++) {
        float logit = acc[r] + bb;
        red[v] = logit;
        __syncthreads();
        if (v == 0) {
            float mx = red[0]; int am = 0;
            for (int q = 1; q < V_; q++) if (red[q] > mx) { mx = red[q]; am = q; }
            smax = mx; sarg = am;
        }
        __syncthreads();
        float e = expf(logit - smax);
        red[v] = e;
        __syncthreads();
        if (v == 0) {
            float s = 0.f;
            for (int q = 0; q < V_; q++) s += red[q];
            ssum = s;
        }
        __syncthreads();
        int m = m0 + r;
        out[(size_t)m * (L_ * V_) + (size_t)l * V_ + v] = e / ssum;
        if (v == 0) {
            tok[m] = sarg;
            if (tokOut) tokOut[(size_t)l * B_ + m] = (float)sarg;
        }
        __syncthreads();
    }
}

// ---------------- init ----------------
__global__ void init_state(float* __restrict__ h, float* __restrict__ c,
                           float* __restrict__ AH, float* __restrict__ AL,
                           int* __restrict__ tok)
{
    int i = blockIdx.x * blockDim.x + threadIdx.x;
    if (i < B_ * H_) { h[i] = 0.f; c[i] = 0.f; AH[i] = 0.f; AL[i] = 0.f; }
    if (i < B_) tok[i] = V_ - 1;
}

// ---------------- launch ----------------
extern "C" void kernel_launch(void* const* d_in, const int* in_sizes, int n_in,
                              void* d_out, int out_size)
{
    int base = 1;
    if (n_in >= 12 && in_sizes[1] == 1) base = 2;

    const int*   inputs  = (const int*)  d_in[0];
    const float* enc_emb = (const float*)d_in[base + 0];
    const float* enc_W   = (const float*)d_in[base + 1];
    const float* enc_U   = (const float*)d_in[base + 2];
    const float* enc_b   = (const float*)d_in[base + 3];
    const float* dec_emb = (const float*)d_in[base + 4];
    const float* dec_W   = (const float*)d_in[base + 5];
    const float* dec_U   = (const float*)d_in[base + 6];
    const float* dec_b   = (const float*)d_in[base + 7];
    const float* out_W   = (const float*)d_in[base + 8];
    const float* out_b   = (const float*)d_in[base + 9];
    float* out = (float*)d_out;

    float *p_h, *p_c, *p_z, *p_AH, *p_AL, *p_EH, *p_EL;
    float *p_BeH, *p_BeL, *p_BdH, *p_BdL, *p_BwH, *p_BwL, *p_encEW, *p_decEW;
    int* p_tok;
    cudaGetSymbolAddress((void**)&p_h, g_h);
    cudaGetSymbolAddress((void**)&p_c, g_c);
    cudaGetSymbolAddress((void**)&p_z, g_z);
    cudaGetSymbolAddress((void**)&p_tok, g_tok);
    cudaGetSymbolAddress((void**)&p_AH, g_AH);
    cudaGetSymbolAddress((void**)&p_AL, g_AL);
    cudaGetSymbolAddress((void**)&p_EH, g_EH);
    cudaGetSymbolAddress((void**)&p_EL, g_EL);
    cudaGetSymbolAddress((void**)&p_BeH, g_BeH);
    cudaGetSymbolAddress((void**)&p_BeL, g_BeL);
    cudaGetSymbolAddress((void**)&p_BdH, g_BdH);
    cudaGetSymbolAddress((void**)&p_BdL, g_BdL);
    cudaGetSymbolAddress((void**)&p_BwH, g_BwH);
    cudaGetSymbolAddress((void**)&p_BwL, g_BwL);
    cudaGetSymbolAddress((void**)&p_encEW, g_encEW);
    cudaGetSymbolAddress((void**)&p_decEW, g_decEW);

    float* tokOut = nullptr;
    if (out_size >= B_ * L_ * V_ + L_ * B_) tokOut = out + (size_t)B_ * L_ * V_;

    cudaFuncSetAttribute(gemm_tc, cudaFuncAttributeMaxDynamicSharedMemorySize, SMEM_BYTES);

    init_state<<<(B_ * H_ + 255) / 256, 256>>>(p_h, p_c, p_AH, p_AL, p_tok);

    dim3 wg(N4H / 32, H_ / 32);

    // ---- table builds (full K in one CTA wave, z=1) ----
    split_weightB<<<wg, 256>>>(enc_W, p_BwH, p_BwL);
    emb_blob<<<32, 256>>>(enc_emb, p_EH, p_EL);
    gemm_tc<<<dim3(64, 1, 1), 256, SMEM_BYTES>>>(p_EH, p_EL, p_BwH, p_BwL,
                                                 enc_b, nullptr, nullptr, 0, NCH, V_, p_encEW);
    split_weightB<<<wg, 256>>>(dec_W, p_BwH, p_BwL);
    emb_blob<<<32, 256>>>(dec_emb, p_EH, p_EL);
    gemm_tc<<<dim3(64, 1, 1), 256, SMEM_BYTES>>>(p_EH, p_EL, p_BwH, p_BwL,
                                                 dec_b, nullptr, nullptr, 0, NCH, V_, p_decEW);
    split_weightB<<<wg, 256>>>(enc_U, p_BeH, p_BeL);
    split_weightB<<<wg, 256>>>(dec_U, p_BdH, p_BdL);

    dim3 gstep(64, 2, 2);   // 256 CTAs, split-K = 2

    // ---- encoder ----
    for (int t = 0; t < T_; t++) {
        gemm_tc<<<gstep, 256, SMEM_BYTES>>>(p_AH, p_AL, p_BeH, p_BeL,
                                            nullptr, p_encEW, inputs + t, T_, NCH / 2, B_, p_z);
        lstm_cell<<<64, 256>>>(p_z, 2, inputs + t, T_, p_h, p_c, p_AH, p_AL);
    }

    // ---- decoder ----
    for (int l = 0; l < L_; l++) {
        gemm_tc<<<gstep, 256, SMEM_BYTES>>>(p_AH, p_AL, p_BdH, p_BdL,
                                            nullptr, p_decEW, p_tok, 1, NCH / 2, B_, p_z);
        lstm_cell<<<64, 256>>>(p_z, 2, p_tok, 1, p_h, p_c, p_AH, p_AL);
        dec_output<<<B_ / 4, V_>>>(p_h, out_W, out_b, out, l, p_tok, tokOut);
    }
}

// round 10
// speedup vs baseline: 1.3442x; 1.3442x over previous
#include <cuda_runtime.h>
#include <cuda_bf16.h>
#include <math.h>
#include <stdint.h>

#define B_   256
#define T_   64
#define H_   1024
#define V_   128
#define L_   32
#define N4H  4096

// ---- GEMM tiling: CTA 128x64, 8 warps (warp 32x32), K=1024 in 32 chunks of 32 ----
// bf16 hi/lo split, mma.m16n8k16 (2 k-steps per chunk)
#define NCH   32
#define ACH_U 2048           // uint32 (bf16x2) per chunk A image (128 rows x 32 k)
#define BCH_U 1024           // uint32 per chunk B image (64 n x 32 k)
#define NSTAGE 4
#define STG_U (2*ACH_U + 2*BCH_U)              // 6144 u32 = 24KB
#define SMEM_BYTES (NSTAGE * STG_U * 4)        // 98304

// ---------------- persistent device scratch ----------------
__device__ float    g_h[B_ * H_];
__device__ float    g_c[B_ * H_];
__device__ float    g_z[B_ * N4H];
__device__ int      g_tok[B_];
__device__ uint32_t g_AH[B_ * H_ / 2];
__device__ uint32_t g_AL[B_ * H_ / 2];
__device__ uint32_t g_EH[V_ * H_ / 2];
__device__ uint32_t g_EL[V_ * H_ / 2];
__device__ uint32_t g_BeH[(size_t)N4H * H_ / 2];
__device__ uint32_t g_BeL[(size_t)N4H * H_ / 2];
__device__ uint32_t g_BdH[(size_t)N4H * H_ / 2];
__device__ uint32_t g_BdL[(size_t)N4H * H_ / 2];
__device__ uint32_t g_BwH[(size_t)N4H * H_ / 2];
__device__ uint32_t g_BwL[(size_t)N4H * H_ / 2];
__device__ float    g_encEW[V_ * N4H];
__device__ float    g_decEW[V_ * N4H];

// ---------------- helpers ----------------
__device__ __forceinline__ uint32_t packb(float lo_elem, float hi_elem) {
    __nv_bfloat162 t = __floats2bfloat162_rn(lo_elem, hi_elem);  // .x = low half
    return *(uint32_t*)&t;
}
// bf16 split of two floats -> packed hi-word and lo-word (element0 in low half)
__device__ __forceinline__ void bsplit2(float x0, float x1, uint32_t& hi, uint32_t& lo) {
    __nv_bfloat16 b0 = __float2bfloat16(x0), b1 = __float2bfloat16(x1);
    float f0 = __bfloat162float(b0), f1 = __bfloat162float(b1);
    __nv_bfloat162 th; th.x = b0; th.y = b1;
    hi = *(uint32_t*)&th;
    lo = packb(x0 - f0, x1 - f1);
}

__device__ __forceinline__ void mma_bf16(float* d, const uint4& a, uint32_t b0, uint32_t b1) {
    asm volatile(
        "mma.sync.aligned.m16n8k16.row.col.f32.bf16.bf16.f32 "
        "{%0,%1,%2,%3}, {%4,%5,%6,%7}, {%8,%9}, {%0,%1,%2,%3};"
        : "+f"(d[0]), "+f"(d[1]), "+f"(d[2]), "+f"(d[3])
        : "r"(a.x), "r"(a.y), "r"(a.z), "r"(a.w), "r"(b0), "r"(b1));
}

__device__ __forceinline__ void cpa16(uint32_t dst, const void* src) {
    asm volatile("cp.async.cg.shared.global [%0], [%1], 16;" :: "r"(dst), "l"(src) : "memory");
}
__device__ __forceinline__ void cpa_commit() {
    asm volatile("cp.async.commit_group;" ::: "memory");
}
template<int N> __device__ __forceinline__ void cpa_wait() {
    asm volatile("cp.async.wait_group %0;" :: "n"(N) : "memory");
}

// Write one (m, m+8) x (j0..j0+7) group into the bf16 A blob.
__device__ __forceinline__ void write_Ablob(uint32_t* AH, uint32_t* AL, int m, int j0,
                                            const float* r0, const float* r1)
{
    int tile = m >> 7, chunk = j0 >> 5, wm_g = (m & 127) >> 5;
    int ks = (j0 & 31) >> 4, half8 = (j0 & 15) >> 3;
    int mf = (m & 31) >> 4, gid = m & 7;
    size_t base = ((size_t)(tile * NCH + chunk)) * ACH_U + (size_t)(((wm_g * 2 + ks) * 2 + mf) * 128);
#pragma unroll
    for (int tig = 0; tig < 4; tig++) {
        int lane = gid * 4 + tig;
        uint32_t pH0, pL0, pH1, pL1;
        bsplit2(r0[2 * tig], r0[2 * tig + 1], pH0, pL0);   // row m   -> a0/a2
        bsplit2(r1[2 * tig], r1[2 * tig + 1], pH1, pL1);   // row m+8 -> a1/a3
        uint2 vh; vh.x = pH0; vh.y = pH1;
        uint2 vl; vl.x = pL0; vl.y = pL1;
        *(uint2*)(AH + base + lane * 4 + half8 * 2) = vh;
        *(uint2*)(AL + base + lane * 4 + half8 * 2) = vl;
    }
}

// ---------------- weight split: W[1024][4096] -> mma-ready bf16 B blob ----------------
__global__ void split_weightB(const float* __restrict__ W,
                              uint32_t* __restrict__ BH, uint32_t* __restrict__ BL)
{
    __shared__ float sH[32][33];
    __shared__ float sL[32][33];
    int n0 = blockIdx.x * 32, k0 = blockIdx.y * 32;
    int tx = threadIdx.x & 31, ty = threadIdx.x >> 5;
#pragma unroll
    for (int i = 0; i < 4; i++) {
        int k = ty + i * 8;
        float x = W[(size_t)(k0 + k) * N4H + n0 + tx];
        __nv_bfloat16 bh = __float2bfloat16(x);
        float hf = __bfloat162float(bh);
        sH[k][tx] = hf;
        sL[k][tx] = __bfloat162float(__float2bfloat16(x - hf));
    }
    __syncthreads();
    int ks   = threadIdx.x >> 7;         // 0..1
    int lane = (threadIdx.x >> 2) & 31;  // 0..31
    int q    = threadIdx.x & 3;          // nf
    int gid = lane >> 2, tig = lane & 3;
    int ncol = q * 8 + gid;
    int kb = ks * 16 + 2 * tig;
    uint32_t b0H = packb(sH[kb][ncol],     sH[kb + 1][ncol]);
    uint32_t b1H = packb(sH[kb + 8][ncol], sH[kb + 9][ncol]);
    uint32_t b0L = packb(sL[kb][ncol],     sL[kb + 1][ncol]);
    uint32_t b1L = packb(sL[kb + 8][ncol], sL[kb + 9][ncol]);
    int tile_n = n0 >> 6, wn_g = (n0 >> 5) & 1, chunk = k0 >> 5;
    size_t ob = ((size_t)(tile_n * NCH + chunk)) * BCH_U + wn_g * 512 + ks * 256 + lane * 8 + q * 2;
    uint2 vh; vh.x = b0H; vh.y = b1H;
    uint2 vl; vl.x = b0L; vl.y = b1L;
    *(uint2*)(BH + ob) = vh;
    *(uint2*)(BL + ob) = vl;
}

// ---------------- emb -> A blob (128 rows, tile 0) ----------------
__global__ void emb_blob(const float* __restrict__ emb,
                         uint32_t* __restrict__ AH, uint32_t* __restrict__ AL)
{
    int t = blockIdx.x * 256 + threadIdx.x;
    if (t >= 8192) return;
    int mp = t >> 7;
    int m  = ((mp >> 3) << 4) | (mp & 7);
    int j0 = (t & 127) << 3;
    float r0[8], r1[8];
    const float* p0 = emb + (size_t)m * H_ + j0;
    const float* p1 = emb + (size_t)(m + 8) * H_ + j0;
#pragma unroll
    for (int i = 0; i < 8; i++) { r0[i] = p0[i]; r1[i] = p1[i]; }
    write_Ablob(AH, AL, m, j0, r0, r1);
}

// ---------------- bf16-split tensor-core step GEMM ----------------
__global__ __launch_bounds__(256)
void gemm_tc(const uint32_t* __restrict__ AH, const uint32_t* __restrict__ AL,
             const uint32_t* __restrict__ BH, const uint32_t* __restrict__ BL,
             const float* __restrict__ bias,
             const float* __restrict__ addTbl, const int* __restrict__ addIdx, int idxStride,
             float* __restrict__ Z)
{
    extern __shared__ uint32_t smu[];
    const int tid = threadIdx.x;
    const int wid = tid >> 5;
    const int lid = tid & 31;
    const int gid = lid >> 2;
    const int tig = lid & 3;
    const int bn  = blockIdx.x * 64;
    const int bm  = blockIdx.y * 128;
    const int wm_g = wid & 3;
    const int wn_g = wid >> 2;

    const uint32_t* AHt = AH + (size_t)blockIdx.y * NCH * ACH_U;
    const uint32_t* ALt = AL + (size_t)blockIdx.y * NCH * ACH_U;
    const uint32_t* BHt = BH + (size_t)blockIdx.x * NCH * BCH_U;
    const uint32_t* BLt = BL + (size_t)blockIdx.x * NCH * BCH_U;

    const uint32_t smb = (uint32_t)__cvta_generic_to_shared(smu);

    auto stage = [&](int s, int cc) {
        uint32_t d = smb + (uint32_t)s * (STG_U * 4);
        const uint32_t* aH = AHt + (size_t)cc * ACH_U;
        const uint32_t* aL = ALt + (size_t)cc * ACH_U;
        const uint32_t* bH = BHt + (size_t)cc * BCH_U;
        const uint32_t* bL = BLt + (size_t)cc * BCH_U;
#pragma unroll
        for (int i = 0; i < 2; i++) {
            int u = tid + i * 256;
            cpa16(d + u * 16,               aH + u * 4);
            cpa16(d + ACH_U * 4 + u * 16,   aL + u * 4);
        }
        cpa16(d + 2 * ACH_U * 4 + tid * 16,               bH + tid * 4);
        cpa16(d + (2 * ACH_U + BCH_U) * 4 + tid * 16,     bL + tid * 4);
        cpa_commit();
    };

    float acc[2][4][4];
#pragma unroll
    for (int mf = 0; mf < 2; mf++)
#pragma unroll
        for (int nf = 0; nf < 4; nf++)
#pragma unroll
            for (int q = 0; q < 4; q++) acc[mf][nf][q] = 0.f;

    stage(0, 0); stage(1, 1); stage(2, 2);

    for (int c = 0; c < NCH; c++) {
        const int s = c & 3;
        cpa_wait<2>();
        __syncthreads();
        if (c + 3 < NCH) stage((c + 3) & 3, c + 3);

        const uint32_t* sAH = smu + s * STG_U;
        const uint32_t* sAL = sAH + ACH_U;
        const uint32_t* sBH = sAH + 2 * ACH_U;
        const uint32_t* sBL = sBH + BCH_U;

#pragma unroll
        for (int ks = 0; ks < 2; ks++) {
            uint4 aH0 = *(const uint4*)(sAH + ((wm_g * 2 + ks) * 2 + 0) * 128 + lid * 4);
            uint4 aH1 = *(const uint4*)(sAH + ((wm_g * 2 + ks) * 2 + 1) * 128 + lid * 4);
            uint4 aL0 = *(const uint4*)(sAL + ((wm_g * 2 + ks) * 2 + 0) * 128 + lid * 4);
            uint4 aL1 = *(const uint4*)(sAL + ((wm_g * 2 + ks) * 2 + 1) * 128 + lid * 4);
            uint4 bh0 = *(const uint4*)(sBH + (wn_g * 2 + ks) * 256 + lid * 8);
            uint4 bh1 = *(const uint4*)(sBH + (wn_g * 2 + ks) * 256 + lid * 8 + 4);
            uint4 bl0 = *(const uint4*)(sBL + (wn_g * 2 + ks) * 256 + lid * 8);
            uint4 bl1 = *(const uint4*)(sBL + (wn_g * 2 + ks) * 256 + lid * 8 + 4);
            uint32_t bH[4][2] = {{bh0.x, bh0.y}, {bh0.z, bh0.w}, {bh1.x, bh1.y}, {bh1.z, bh1.w}};
            uint32_t bL[4][2] = {{bl0.x, bl0.y}, {bl0.z, bl0.w}, {bl1.x, bl1.y}, {bl1.z, bl1.w}};
            // HH pass (8 distinct accumulators)
#pragma unroll
            for (int nf = 0; nf < 4; nf++) {
                mma_bf16(acc[0][nf], aH0, bH[nf][0], bH[nf][1]);
                mma_bf16(acc[1][nf], aH1, bH[nf][0], bH[nf][1]);
            }
            // HL pass
#pragma unroll
            for (int nf = 0; nf < 4; nf++) {
                mma_bf16(acc[0][nf], aH0, bL[nf][0], bL[nf][1]);
                mma_bf16(acc[1][nf], aH1, bL[nf][0], bL[nf][1]);
            }
            // LH pass
#pragma unroll
            for (int nf = 0; nf < 4; nf++) {
                mma_bf16(acc[0][nf], aL0, bH[nf][0], bH[nf][1]);
                mma_bf16(acc[1][nf], aL1, bH[nf][0], bH[nf][1]);
            }
        }
    }

    // ---- epilogue ----
#pragma unroll
    for (int mf = 0; mf < 2; mf++) {
#pragma unroll
        for (int half = 0; half < 2; half++) {
            int m = bm + wm_g * 32 + mf * 16 + half * 8 + gid;
            const float* arow = addTbl ? (addTbl + (size_t)addIdx[(size_t)m * idxStride] * N4H) : nullptr;
            float* zrow = Z + (size_t)m * N4H;
#pragma unroll
            for (int nf = 0; nf < 4; nf++) {
                int cn = bn + wn_g * 32 + nf * 8 + tig * 2;
                float v0 = acc[mf][nf][half * 2 + 0];
                float v1 = acc[mf][nf][half * 2 + 1];
                if (bias) { v0 += bias[cn]; v1 += bias[cn + 1]; }
                if (arow) { v0 += arow[cn]; v1 += arow[cn + 1]; }
                float2 o; o.x = v0; o.y = v1;
                *(float2*)(zrow + cn) = o;
            }
        }
    }
}

// ---------------- LSTM cell: gates + masked update + bf16 blob emit ----------------
__global__ void lstm_cell(const float* __restrict__ Z,
                          const int* __restrict__ maskSrc, int maskStride,
                          float* __restrict__ h, float* __restrict__ c,
                          uint32_t* __restrict__ AH, uint32_t* __restrict__ AL)
{
    int t = blockIdx.x * blockDim.x + threadIdx.x;
    if (t >= 16384) return;
    int mp = t >> 7;
    int m  = ((mp >> 3) << 4) | (mp & 7);
    int j0 = (t & 127) << 3;

    float hv[2][8];
#pragma unroll
    for (int half = 0; half < 2; half++) {
        int mm = m + half * 8;
        bool act = maskSrc[(size_t)mm * maskStride] != 0;
        if (act) {
            const float* zr = Z + (size_t)mm * N4H + j0;
            float* cp = c + (size_t)mm * H_ + j0;
            float* hp = h + (size_t)mm * H_ + j0;
            float4 hout[2], cout[2];
#pragma unroll
            for (int q = 0; q < 8; q++) {
                float vi = zr[q];        float vf = zr[1024 + q];
                float vg = zr[2048 + q]; float vo = zr[3072 + q];
                float vc = cp[q];
                float ig = 1.0f / (1.0f + expf(-vi));
                float fg = 1.0f / (1.0f + expf(-vf));
                float gg = tanhf(vg);
                float og = 1.0f / (1.0f + expf(-vo));
                float c2 = fg * vc + ig * gg;
                float h2 = og * tanhf(c2);
                ((float*)&cout[q >> 2].x)[q & 3] = c2;
                ((float*)&hout[q >> 2].x)[q & 3] = h2;
                hv[half][q] = h2;
            }
            *(float4*)(cp)     = cout[0];
            *(float4*)(cp + 4) = cout[1];
            *(float4*)(hp)     = hout[0];
            *(float4*)(hp + 4) = hout[1];
        } else {
            const float* hp = h + (size_t)mm * H_ + j0;
#pragma unroll
            for (int q = 0; q < 8; q++) hv[half][q] = hp[q];
        }
    }
    write_Ablob(AH, AL, m, j0, hv[0], hv[1]);
}

// ---------------- decoder output: logits + softmax + argmax ----------------
__global__ void dec_output(const float* __restrict__ h,
                           const float* __restrict__ outW, const float* __restrict__ outb,
                           float* __restrict__ out, int l,
                           int* __restrict__ tok, float* __restrict__ tokOut)
{
    const int ROWS = 4;
    __shared__ float hs[ROWS][H_];
    __shared__ float red[V_];
    __shared__ float smax, ssum;
    __shared__ int   sarg;

    int m0 = blockIdx.x * ROWS;
    int v  = threadIdx.x;

    for (int idx = threadIdx.x; idx < ROWS * H_; idx += blockDim.x) {
        int r = idx >> 10;
        hs[r][idx & 1023] = h[(size_t)(m0 + r) * H_ + (idx & 1023)];
    }
    __syncthreads();

    float acc[ROWS] = {0.f, 0.f, 0.f, 0.f};
#pragma unroll 8
    for (int k = 0; k < H_; k++) {
        float w = outW[(size_t)k * V_ + v];
#pragma unroll
        for (int r = 0; r < ROWS; r++) acc[r] += hs[r][k] * w;
    }
    float bb = outb[v];

    for (int r = 0; r < ROWS; r++) {
        float logit = acc[r] + bb;
        red[v] = logit;
        __syncthreads();
        if (v == 0) {
            float mx = red[0]; int am = 0;
            for (int q = 1; q < V_; q++) if (red[q] > mx) { mx = red[q]; am = q; }
            smax = mx; sarg = am;
        }
        __syncthreads();
        float e = expf(logit - smax);
        red[v] = e;
        __syncthreads();
        if (v == 0) {
            float s = 0.f;
            for (int q = 0; q < V_; q++) s += red[q];
            ssum = s;
        }
        __syncthreads();
        int m = m0 + r;
        out[(size_t)m * (L_ * V_) + (size_t)l * V_ + v] = e / ssum;
        if (v == 0) {
            tok[m] = sarg;
            if (tokOut) tokOut[(size_t)l * B_ + m] = (float)sarg;
        }
        __syncthreads();
    }
}

// ---------------- init ----------------
__global__ void init_state(float* __restrict__ h, float* __restrict__ c,
                           uint32_t* __restrict__ AH, uint32_t* __restrict__ AL,
                           int* __restrict__ tok)
{
    int i = blockIdx.x * blockDim.x + threadIdx.x;
    if (i < B_ * H_) { h[i] = 0.f; c[i] = 0.f; }
    if (i < B_ * H_ / 2) { AH[i] = 0u; AL[i] = 0u; }
    if (i < B_) tok[i] = V_ - 1;
}

// ---------------- launch ----------------
extern "C" void kernel_launch(void* const* d_in, const int* in_sizes, int n_in,
                              void* d_out, int out_size)
{
    int base = 1;
    if (n_in >= 12 && in_sizes[1] == 1) base = 2;

    const int*   inputs  = (const int*)  d_in[0];
    const float* enc_emb = (const float*)d_in[base + 0];
    const float* enc_W   = (const float*)d_in[base + 1];
    const float* enc_U   = (const float*)d_in[base + 2];
    const float* enc_b   = (const float*)d_in[base + 3];
    const float* dec_emb = (const float*)d_in[base + 4];
    const float* dec_W   = (const float*)d_in[base + 5];
    const float* dec_U   = (const float*)d_in[base + 6];
    const float* dec_b   = (const float*)d_in[base + 7];
    const float* out_W   = (const float*)d_in[base + 8];
    const float* out_b   = (const float*)d_in[base + 9];
    float* out = (float*)d_out;

    float *p_h, *p_c, *p_z, *p_encEW, *p_decEW;
    uint32_t *p_AH, *p_AL, *p_EH, *p_EL, *p_BeH, *p_BeL, *p_BdH, *p_BdL, *p_BwH, *p_BwL;
    int* p_tok;
    cudaGetSymbolAddress((void**)&p_h, g_h);
    cudaGetSymbolAddress((void**)&p_c, g_c);
    cudaGetSymbolAddress((void**)&p_z, g_z);
    cudaGetSymbolAddress((void**)&p_tok, g_tok);
    cudaGetSymbolAddress((void**)&p_AH, g_AH);
    cudaGetSymbolAddress((void**)&p_AL, g_AL);
    cudaGetSymbolAddress((void**)&p_EH, g_EH);
    cudaGetSymbolAddress((void**)&p_EL, g_EL);
    cudaGetSymbolAddress((void**)&p_BeH, g_BeH);
    cudaGetSymbolAddress((void**)&p_BeL, g_BeL);
    cudaGetSymbolAddress((void**)&p_BdH, g_BdH);
    cudaGetSymbolAddress((void**)&p_BdL, g_BdL);
    cudaGetSymbolAddress((void**)&p_BwH, g_BwH);
    cudaGetSymbolAddress((void**)&p_BwL, g_BwL);
    cudaGetSymbolAddress((void**)&p_encEW, g_encEW);
    cudaGetSymbolAddress((void**)&p_decEW, g_decEW);

    float* tokOut = nullptr;
    if (out_size >= B_ * L_ * V_ + L_ * B_) tokOut = out + (size_t)B_ * L_ * V_;

    cudaFuncSetAttribute(gemm_tc, cudaFuncAttributeMaxDynamicSharedMemorySize, SMEM_BYTES);

    init_state<<<(B_ * H_ + 255) / 256, 256>>>(p_h, p_c, p_AH, p_AL, p_tok);

    dim3 wg(N4H / 32, H_ / 32);

    // ---- table builds ----
    split_weightB<<<wg, 256>>>(enc_W, p_BwH, p_BwL);
    emb_blob<<<32, 256>>>(enc_emb, p_EH, p_EL);
    gemm_tc<<<dim3(64, 1), 256, SMEM_BYTES>>>(p_EH, p_EL, p_BwH, p_BwL,
                                              enc_b, nullptr, nullptr, 0, p_encEW);
    split_weightB<<<wg, 256>>>(dec_W, p_BwH, p_BwL);
    emb_blob<<<32, 256>>>(dec_emb, p_EH, p_EL);
    gemm_tc<<<dim3(64, 1), 256, SMEM_BYTES>>>(p_EH, p_EL, p_BwH, p_BwL,
                                              dec_b, nullptr, nullptr, 0, p_decEW);
    split_weightB<<<wg, 256>>>(enc_U, p_BeH, p_BeL);
    split_weightB<<<wg, 256>>>(dec_U, p_BdH, p_BdL);

    dim3 gstep(64, 2);   // 128 CTAs

    // ---- encoder ----
    for (int t = 0; t < T_; t++) {
        gemm_tc<<<gstep, 256, SMEM_BYTES>>>(p_AH, p_AL, p_BeH, p_BeL,
                                            nullptr, p_encEW, inputs + t, T_, p_z);
        lstm_cell<<<64, 256>>>(p_z, inputs + t, T_, p_h, p_c, p_AH, p_AL);
    }

    // ---- decoder ----
    for (int l = 0; l < L_; l++) {
        gemm_tc<<<gstep, 256, SMEM_BYTES>>>(p_AH, p_AL, p_BdH, p_BdL,
                                            nullptr, p_decEW, p_tok, 1, p_z);
        lstm_cell<<<64, 256>>>(p_z, p_tok, 1, p_h, p_c, p_AH, p_AL);
        dec_output<<<B_ / 4, V_>>>(p_h, out_W, out_b, out, l, p_tok, tokOut);
    }
}

// round 11
// speedup vs baseline: 1.3517x; 1.0056x over previous
#include <cuda_runtime.h>
#include <cuda_bf16.h>
#include <math.h>
#include <stdint.h>

#define B_   256
#define T_   64
#define H_   1024
#define V_   128
#define L_   32
#define N4H  4096

// ---- GEMM tiling: CTA 128x64, 8 warps (warp 32x32), K=1024 in 32 chunks of 32 ----
// bf16 hi/lo split, mma.m16n8k16; staging via cp.async.bulk + mbarrier
#define NCH   32
#define ACH_U 2048           // uint32 (bf16x2) per chunk A image (128 rows x 32 k)
#define BCH_U 1024           // uint32 per chunk B image (64 n x 32 k)
#define NSTAGE 4
#define STG_U (2*ACH_U + 2*BCH_U)              // 6144 u32 = 24KB
#define STG_BYTES (STG_U * 4)
#define SMEM_BYTES (1024 + NSTAGE * STG_BYTES) // 99328

// ---------------- persistent device scratch ----------------
__device__ float    g_h[B_ * H_];
__device__ float    g_c[B_ * H_];
__device__ float    g_z[B_ * N4H];
__device__ int      g_tok[B_];
__device__ uint32_t g_AH[B_ * H_ / 2];
__device__ uint32_t g_AL[B_ * H_ / 2];
__device__ uint32_t g_EH[V_ * H_ / 2];
__device__ uint32_t g_EL[V_ * H_ / 2];
__device__ uint32_t g_BeH[(size_t)N4H * H_ / 2];
__device__ uint32_t g_BeL[(size_t)N4H * H_ / 2];
__device__ uint32_t g_BdH[(size_t)N4H * H_ / 2];
__device__ uint32_t g_BdL[(size_t)N4H * H_ / 2];
__device__ uint32_t g_BwH[(size_t)N4H * H_ / 2];
__device__ uint32_t g_BwL[(size_t)N4H * H_ / 2];
__device__ float    g_encEW[V_ * N4H];
__device__ float    g_decEW[V_ * N4H];

// ---------------- helpers ----------------
__device__ __forceinline__ uint32_t packb(float lo_elem, float hi_elem) {
    __nv_bfloat162 t = __floats2bfloat162_rn(lo_elem, hi_elem);  // .x = low half
    return *(uint32_t*)&t;
}
__device__ __forceinline__ void bsplit2(float x0, float x1, uint32_t& hi, uint32_t& lo) {
    __nv_bfloat16 b0 = __float2bfloat16(x0), b1 = __float2bfloat16(x1);
    float f0 = __bfloat162float(b0), f1 = __bfloat162float(b1);
    __nv_bfloat162 th; th.x = b0; th.y = b1;
    hi = *(uint32_t*)&th;
    lo = packb(x0 - f0, x1 - f1);
}

__device__ __forceinline__ void mma_bf16(float* d, const uint4& a, uint32_t b0, uint32_t b1) {
    asm volatile(
        "mma.sync.aligned.m16n8k16.row.col.f32.bf16.bf16.f32 "
        "{%0,%1,%2,%3}, {%4,%5,%6,%7}, {%8,%9}, {%0,%1,%2,%3};"
        : "+f"(d[0]), "+f"(d[1]), "+f"(d[2]), "+f"(d[3])
        : "r"(a.x), "r"(a.y), "r"(a.z), "r"(a.w), "r"(b0), "r"(b1));
}

__device__ __forceinline__ void mbar_init(uint32_t a, uint32_t cnt) {
    asm volatile("mbarrier.init.shared.b64 [%0], %1;" :: "r"(a), "r"(cnt) : "memory");
}
__device__ __forceinline__ void mbar_expect_tx(uint32_t a, uint32_t bytes) {
    asm volatile("mbarrier.arrive.expect_tx.shared.b64 _, [%0], %1;" :: "r"(a), "r"(bytes) : "memory");
}
__device__ __forceinline__ void mbar_wait(uint32_t a, uint32_t ph) {
    asm volatile(
        "{\n\t.reg .pred P;\n\t"
        "W%=:\n\t"
        "mbarrier.try_wait.parity.acquire.cta.shared::cta.b64 P, [%0], %1, 0x989680;\n\t"
        "@!P bra W%=;\n\t}"
        :: "r"(a), "r"(ph) : "memory");
}
__device__ __forceinline__ void bulk_cp(uint32_t dst, const void* src, uint32_t bytes, uint32_t mbar) {
    asm volatile(
        "cp.async.bulk.shared::cluster.global.mbarrier::complete_tx::bytes [%0], [%1], %2, [%3];"
        :: "r"(dst), "l"(src), "r"(bytes), "r"(mbar) : "memory");
}

// Write one (m, m+8) x (j0..j0+7) group into the bf16 A blob.
__device__ __forceinline__ void write_Ablob(uint32_t* AH, uint32_t* AL, int m, int j0,
                                            const float* r0, const float* r1)
{
    int tile = m >> 7, chunk = j0 >> 5, wm_g = (m & 127) >> 5;
    int ks = (j0 & 31) >> 4, half8 = (j0 & 15) >> 3;
    int mf = (m & 31) >> 4, gid = m & 7;
    size_t base = ((size_t)(tile * NCH + chunk)) * ACH_U + (size_t)(((wm_g * 2 + ks) * 2 + mf) * 128);
#pragma unroll
    for (int tig = 0; tig < 4; tig++) {
        int lane = gid * 4 + tig;
        uint32_t pH0, pL0, pH1, pL1;
        bsplit2(r0[2 * tig], r0[2 * tig + 1], pH0, pL0);
        bsplit2(r1[2 * tig], r1[2 * tig + 1], pH1, pL1);
        uint2 vh; vh.x = pH0; vh.y = pH1;
        uint2 vl; vl.x = pL0; vl.y = pL1;
        *(uint2*)(AH + base + lane * 4 + half8 * 2) = vh;
        *(uint2*)(AL + base + lane * 4 + half8 * 2) = vl;
    }
}

// ---------------- weight split: W[1024][4096] -> mma-ready bf16 B blob ----------------
__global__ void split_weightB(const float* __restrict__ W,
                              uint32_t* __restrict__ BH, uint32_t* __restrict__ BL)
{
    __shared__ float sH[32][33];
    __shared__ float sL[32][33];
    int n0 = blockIdx.x * 32, k0 = blockIdx.y * 32;
    int tx = threadIdx.x & 31, ty = threadIdx.x >> 5;
#pragma unroll
    for (int i = 0; i < 4; i++) {
        int k = ty + i * 8;
        float x = W[(size_t)(k0 + k) * N4H + n0 + tx];
        __nv_bfloat16 bh = __float2bfloat16(x);
        float hf = __bfloat162float(bh);
        sH[k][tx] = hf;
        sL[k][tx] = __bfloat162float(__float2bfloat16(x - hf));
    }
    __syncthreads();
    int ks   = threadIdx.x >> 7;
    int lane = (threadIdx.x >> 2) & 31;
    int q    = threadIdx.x & 3;
    int gid = lane >> 2, tig = lane & 3;
    int ncol = q * 8 + gid;
    int kb = ks * 16 + 2 * tig;
    uint32_t b0H = packb(sH[kb][ncol],     sH[kb + 1][ncol]);
    uint32_t b1H = packb(sH[kb + 8][ncol], sH[kb + 9][ncol]);
    uint32_t b0L = packb(sL[kb][ncol],     sL[kb + 1][ncol]);
    uint32_t b1L = packb(sL[kb + 8][ncol], sL[kb + 9][ncol]);
    int tile_n = n0 >> 6, wn_g = (n0 >> 5) & 1, chunk = k0 >> 5;
    size_t ob = ((size_t)(tile_n * NCH + chunk)) * BCH_U + wn_g * 512 + ks * 256 + lane * 8 + q * 2;
    uint2 vh; vh.x = b0H; vh.y = b1H;
    uint2 vl; vl.x = b0L; vl.y = b1L;
    *(uint2*)(BH + ob) = vh;
    *(uint2*)(BL + ob) = vl;
}

// ---------------- emb -> A blob (128 rows, tile 0) ----------------
__global__ void emb_blob(const float* __restrict__ emb,
                         uint32_t* __restrict__ AH, uint32_t* __restrict__ AL)
{
    int t = blockIdx.x * 256 + threadIdx.x;
    if (t >= 8192) return;
    int mp = t >> 7;
    int m  = ((mp >> 3) << 4) | (mp & 7);
    int j0 = (t & 127) << 3;
    float r0[8], r1[8];
    const float* p0 = emb + (size_t)m * H_ + j0;
    const float* p1 = emb + (size_t)(m + 8) * H_ + j0;
#pragma unroll
    for (int i = 0; i < 8; i++) { r0[i] = p0[i]; r1[i] = p1[i]; }
    write_Ablob(AH, AL, m, j0, r0, r1);
}

// ---------------- bf16-split tensor-core step GEMM (bulk-async staging) ----------------
__global__ __launch_bounds__(256)
void gemm_tc(const uint32_t* __restrict__ AH, const uint32_t* __restrict__ AL,
             const uint32_t* __restrict__ BH, const uint32_t* __restrict__ BL,
             const float* __restrict__ bias,
             const float* __restrict__ addTbl, const int* __restrict__ addIdx, int idxStride,
             float* __restrict__ Z)
{
    extern __shared__ uint32_t smu[];
    const int tid = threadIdx.x;
    const int wid = tid >> 5;
    const int lid = tid & 31;
    const int gid = lid >> 2;
    const int tig = lid & 3;
    const int bn  = blockIdx.x * 64;
    const int bm  = blockIdx.y * 128;
    const int wm_g = wid & 3;
    const int wn_g = wid >> 2;

    const uint32_t* AHt = AH + (size_t)blockIdx.y * NCH * ACH_U;
    const uint32_t* ALt = AL + (size_t)blockIdx.y * NCH * ACH_U;
    const uint32_t* BHt = BH + (size_t)blockIdx.x * NCH * BCH_U;
    const uint32_t* BLt = BL + (size_t)blockIdx.x * NCH * BCH_U;

    const uint32_t smb = (uint32_t)__cvta_generic_to_shared(smu);
    const uint32_t mb_base  = smb;          // 4 mbarriers
    const uint32_t dat_base = smb + 1024;

    if (tid == 0) {
#pragma unroll
        for (int s = 0; s < NSTAGE; s++) mbar_init(mb_base + s * 8, 1);
        asm volatile("fence.proxy.async.shared::cta;" ::: "memory");
    }
    __syncthreads();

    auto issue = [&](int cc) {
        if (tid != 0) return;
        int s = cc & 3;
        uint32_t mb = mb_base + s * 8;
        uint32_t d  = dat_base + s * STG_BYTES;
        mbar_expect_tx(mb, STG_BYTES);
        bulk_cp(d,                  AHt + (size_t)cc * ACH_U, ACH_U * 4, mb);
        bulk_cp(d + ACH_U * 4,      ALt + (size_t)cc * ACH_U, ACH_U * 4, mb);
        bulk_cp(d + 2 * ACH_U * 4,  BHt + (size_t)cc * BCH_U, BCH_U * 4, mb);
        bulk_cp(d + 2 * ACH_U * 4 + BCH_U * 4, BLt + (size_t)cc * BCH_U, BCH_U * 4, mb);
    };

    float acc[2][4][4];
#pragma unroll
    for (int mf = 0; mf < 2; mf++)
#pragma unroll
        for (int nf = 0; nf < 4; nf++)
#pragma unroll
            for (int q = 0; q < 4; q++) acc[mf][nf][q] = 0.f;

    issue(0); issue(1); issue(2);

    for (int c = 0; c < NCH; c++) {
        const int s = c & 3;
        mbar_wait(mb_base + s * 8, (c >> 2) & 1);

        const uint32_t* sAH = smu + 256 + s * STG_U;
        const uint32_t* sAL = sAH + ACH_U;
        const uint32_t* sBH = sAL + ACH_U;
        const uint32_t* sBL = sBH + BCH_U;

#pragma unroll
        for (int ks = 0; ks < 2; ks++) {
            uint4 aH0 = *(const uint4*)(sAH + ((wm_g * 2 + ks) * 2 + 0) * 128 + lid * 4);
            uint4 aH1 = *(const uint4*)(sAH + ((wm_g * 2 + ks) * 2 + 1) * 128 + lid * 4);
            uint4 aL0 = *(const uint4*)(sAL + ((wm_g * 2 + ks) * 2 + 0) * 128 + lid * 4);
            uint4 aL1 = *(const uint4*)(sAL + ((wm_g * 2 + ks) * 2 + 1) * 128 + lid * 4);
            uint4 bh0 = *(const uint4*)(sBH + (wn_g * 2 + ks) * 256 + lid * 8);
            uint4 bh1 = *(const uint4*)(sBH + (wn_g * 2 + ks) * 256 + lid * 8 + 4);
            uint4 bl0 = *(const uint4*)(sBL + (wn_g * 2 + ks) * 256 + lid * 8);
            uint4 bl1 = *(const uint4*)(sBL + (wn_g * 2 + ks) * 256 + lid * 8 + 4);
            uint32_t bH[4][2] = {{bh0.x, bh0.y}, {bh0.z, bh0.w}, {bh1.x, bh1.y}, {bh1.z, bh1.w}};
            uint32_t bL[4][2] = {{bl0.x, bl0.y}, {bl0.z, bl0.w}, {bl1.x, bl1.y}, {bl1.z, bl1.w}};
#pragma unroll
            for (int nf = 0; nf < 4; nf++) {
                mma_bf16(acc[0][nf], aH0, bH[nf][0], bH[nf][1]);
                mma_bf16(acc[1][nf], aH1, bH[nf][0], bH[nf][1]);
            }
#pragma unroll
            for (int nf = 0; nf < 4; nf++) {
                mma_bf16(acc[0][nf], aH0, bL[nf][0], bL[nf][1]);
                mma_bf16(acc[1][nf], aH1, bL[nf][0], bL[nf][1]);
            }
#pragma unroll
            for (int nf = 0; nf < 4; nf++) {
                mma_bf16(acc[0][nf], aL0, bH[nf][0], bH[nf][1]);
                mma_bf16(acc[1][nf], aL1, bH[nf][0], bH[nf][1]);
            }
        }
        __syncthreads();
        if (c + 3 < NCH) issue(c + 3);
    }

    // ---- epilogue ----
#pragma unroll
    for (int mf = 0; mf < 2; mf++) {
#pragma unroll
        for (int half = 0; half < 2; half++) {
            int m = bm + wm_g * 32 + mf * 16 + half * 8 + gid;
            const float* arow = addTbl ? (addTbl + (size_t)addIdx[(size_t)m * idxStride] * N4H) : nullptr;
            float* zrow = Z + (size_t)m * N4H;
#pragma unroll
            for (int nf = 0; nf < 4; nf++) {
                int cn = bn + wn_g * 32 + nf * 8 + tig * 2;
                float v0 = acc[mf][nf][half * 2 + 0];
                float v1 = acc[mf][nf][half * 2 + 1];
                if (bias) { v0 += bias[cn]; v1 += bias[cn + 1]; }
                if (arow) { v0 += arow[cn]; v1 += arow[cn + 1]; }
                float2 o; o.x = v0; o.y = v1;
                *(float2*)(zrow + cn) = o;
            }
        }
    }
}

// ---------------- LSTM cell: gates + masked update + bf16 blob emit ----------------
__global__ void lstm_cell(const float* __restrict__ Z,
                          const int* __restrict__ maskSrc, int maskStride,
                          float* __restrict__ h, float* __restrict__ c,
                          uint32_t* __restrict__ AH, uint32_t* __restrict__ AL)
{
    int t = blockIdx.x * blockDim.x + threadIdx.x;
    if (t >= 16384) return;
    int mp = t >> 7;
    int m  = ((mp >> 3) << 4) | (mp & 7);
    int j0 = (t & 127) << 3;

    float hv[2][8];
#pragma unroll
    for (int half = 0; half < 2; half++) {
        int mm = m + half * 8;
        bool act = maskSrc[(size_t)mm * maskStride] != 0;
        if (act) {
            const float* zr = Z + (size_t)mm * N4H + j0;
            float* cp = c + (size_t)mm * H_ + j0;
            float* hp = h + (size_t)mm * H_ + j0;
            float4 hout[2], cout[2];
#pragma unroll
            for (int q = 0; q < 8; q++) {
                float vi = zr[q];        float vf = zr[1024 + q];
                float vg = zr[2048 + q]; float vo = zr[3072 + q];
                float vc = cp[q];
                float ig = 1.0f / (1.0f + expf(-vi));
                float fg = 1.0f / (1.0f + expf(-vf));
                float gg = tanhf(vg);
                float og = 1.0f / (1.0f + expf(-vo));
                float c2 = fg * vc + ig * gg;
                float h2 = og * tanhf(c2);
                ((float*)&cout[q >> 2].x)[q & 3] = c2;
                ((float*)&hout[q >> 2].x)[q & 3] = h2;
                hv[half][q] = h2;
            }
            *(float4*)(cp)     = cout[0];
            *(float4*)(cp + 4) = cout[1];
            *(float4*)(hp)     = hout[0];
            *(float4*)(hp + 4) = hout[1];
        } else {
            const float* hp = h + (size_t)mm * H_ + j0;
#pragma unroll
            for (int q = 0; q < 8; q++) hv[half][q] = hp[q];
        }
    }
    write_Ablob(AH, AL, m, j0, hv[0], hv[1]);
}

// ---------------- decoder output: logits + softmax + argmax ----------------
__global__ void dec_output(const float* __restrict__ h,
                           const float* __restrict__ outW, const float* __restrict__ outb,
                           float* __restrict__ out, int l,
                           int* __restrict__ tok, float* __restrict__ tokOut)
{
    const int ROWS = 4;
    __shared__ float hs[ROWS][H_];
    __shared__ float red[V_];
    __shared__ float smax, ssum;
    __shared__ int   sarg;

    int m0 = blockIdx.x * ROWS;
    int v  = threadIdx.x;

    for (int idx = threadIdx.x; idx < ROWS * H_; idx += blockDim.x) {
        int r = idx >> 10;
        hs[r][idx & 1023] = h[(size_t)(m0 + r) * H_ + (idx & 1023)];
    }
    __syncthreads();

    float acc[ROWS] = {0.f, 0.f, 0.f, 0.f};
#pragma unroll 8
    for (int k = 0; k < H_; k++) {
        float w = outW[(size_t)k * V_ + v];
#pragma unroll
        for (int r = 0; r < ROWS; r++) acc[r] += hs[r][k] * w;
    }
    float bb = outb[v];

    for (int r = 0; r < ROWS; r++) {
        float logit = acc[r] + bb;
        red[v] = logit;
        __syncthreads();
        if (v == 0) {
            float mx = red[0]; int am = 0;
            for (int q = 1; q < V_; q++) if (red[q] > mx) { mx = red[q]; am = q; }
            smax = mx; sarg = am;
        }
        __syncthreads();
        float e = expf(logit - smax);
        red[v] = e;
        __syncthreads();
        if (v == 0) {
            float s = 0.f;
            for (int q = 0; q < V_; q++) s += red[q];
            ssum = s;
        }
        __syncthreads();
        int m = m0 + r;
        out[(size_t)m * (L_ * V_) + (size_t)l * V_ + v] = e / ssum;
        if (v == 0) {
            tok[m] = sarg;
            if (tokOut) tokOut[(size_t)l * B_ + m] = (float)sarg;
        }
        __syncthreads();
    }
}

// ---------------- init ----------------
__global__ void init_state(float* __restrict__ h, float* __restrict__ c,
                           uint32_t* __restrict__ AH, uint32_t* __restrict__ AL,
                           int* __restrict__ tok)
{
    int i = blockIdx.x * blockDim.x + threadIdx.x;
    if (i < B_ * H_) { h[i] = 0.f; c[i] = 0.f; }
    if (i < B_ * H_ / 2) { AH[i] = 0u; AL[i] = 0u; }
    if (i < B_) tok[i] = V_ - 1;
}

// ---------------- launch ----------------
extern "C" void kernel_launch(void* const* d_in, const int* in_sizes, int n_in,
                              void* d_out, int out_size)
{
    int base = 1;
    if (n_in >= 12 && in_sizes[1] == 1) base = 2;

    const int*   inputs  = (const int*)  d_in[0];
    const float* enc_emb = (const float*)d_in[base + 0];
    const float* enc_W   = (const float*)d_in[base + 1];
    const float* enc_U   = (const float*)d_in[base + 2];
    const float* enc_b   = (const float*)d_in[base + 3];
    const float* dec_emb = (const float*)d_in[base + 4];
    const float* dec_W   = (const float*)d_in[base + 5];
    const float* dec_U   = (const float*)d_in[base + 6];
    const float* dec_b   = (const float*)d_in[base + 7];
    const float* out_W   = (const float*)d_in[base + 8];
    const float* out_b   = (const float*)d_in[base + 9];
    float* out = (float*)d_out;

    float *p_h, *p_c, *p_z, *p_encEW, *p_decEW;
    uint32_t *p_AH, *p_AL, *p_EH, *p_EL, *p_BeH, *p_BeL, *p_BdH, *p_BdL, *p_BwH, *p_BwL;
    int* p_tok;
    cudaGetSymbolAddress((void**)&p_h, g_h);
    cudaGetSymbolAddress((void**)&p_c, g_c);
    cudaGetSymbolAddress((void**)&p_z, g_z);
    cudaGetSymbolAddress((void**)&p_tok, g_tok);
    cudaGetSymbolAddress((void**)&p_AH, g_AH);
    cudaGetSymbolAddress((void**)&p_AL, g_AL);
    cudaGetSymbolAddress((void**)&p_EH, g_EH);
    cudaGetSymbolAddress((void**)&p_EL, g_EL);
    cudaGetSymbolAddress((void**)&p_BeH, g_BeH);
    cudaGetSymbolAddress((void**)&p_BeL, g_BeL);
    cudaGetSymbolAddress((void**)&p_BdH, g_BdH);
    cudaGetSymbolAddress((void**)&p_BdL, g_BdL);
    cudaGetSymbolAddress((void**)&p_BwH, g_BwH);
    cudaGetSymbolAddress((void**)&p_BwL, g_BwL);
    cudaGetSymbolAddress((void**)&p_encEW, g_encEW);
    cudaGetSymbolAddress((void**)&p_decEW, g_decEW);

    float* tokOut = nullptr;
    if (out_size >= B_ * L_ * V_ + L_ * B_) tokOut = out + (size_t)B_ * L_ * V_;

    cudaFuncSetAttribute(gemm_tc, cudaFuncAttributeMaxDynamicSharedMemorySize, SMEM_BYTES);

    init_state<<<(B_ * H_ + 255) / 256, 256>>>(p_h, p_c, p_AH, p_AL, p_tok);

    dim3 wg(N4H / 32, H_ / 32);

    // ---- table builds ----
    split_weightB<<<wg, 256>>>(enc_W, p_BwH, p_BwL);
    emb_blob<<<32, 256>>>(enc_emb, p_EH, p_EL);
    gemm_tc<<<dim3(64, 1), 256, SMEM_BYTES>>>(p_EH, p_EL, p_BwH, p_BwL,
                                              enc_b, nullptr, nullptr, 0, p_encEW);
    split_weightB<<<wg, 256>>>(dec_W, p_BwH, p_BwL);
    emb_blob<<<32, 256>>>(dec_emb, p_EH, p_EL);
    gemm_tc<<<dim3(64, 1), 256, SMEM_BYTES>>>(p_EH, p_EL, p_BwH, p_BwL,
                                              dec_b, nullptr, nullptr, 0, p_decEW);
    split_weightB<<<wg, 256>>>(enc_U, p_BeH, p_BeL);
    split_weightB<<<wg, 256>>>(dec_U, p_BdH, p_BdL);

    dim3 gstep(64, 2);   // 128 CTAs

    // ---- encoder ----
    for (int t = 0; t < T_; t++) {
        gemm_tc<<<gstep, 256, SMEM_BYTES>>>(p_AH, p_AL, p_BeH, p_BeL,
                                            nullptr, p_encEW, inputs + t, T_, p_z);
        lstm_cell<<<64, 256>>>(p_z, inputs + t, T_, p_h, p_c, p_AH, p_AL);
    }

    // ---- decoder ----
    for (int l = 0; l < L_; l++) {
        gemm_tc<<<gstep, 256, SMEM_BYTES>>>(p_AH, p_AL, p_BdH, p_BdL,
                                            nullptr, p_decEW, p_tok, 1, p_z);
        lstm_cell<<<64, 256>>>(p_z, p_tok, 1, p_h, p_c, p_AH, p_AL);
        dec_output<<<B_ / 4, V_>>>(p_h, out_W, out_b, out, l, p_tok, tokOut);
    }
}

// round 12
// speedup vs baseline: 1.4229x; 1.0526x over previous
#include <cuda_runtime.h>
#include <cuda_bf16.h>
#include <math.h>
#include <stdint.h>

#define B_   256
#define T_   64
#define H_   1024
#define V_   128
#define L_   32
#define N4H  4096

// ---- GEMM tiling: CTA 128x64, 8 warps (warp 32x32), K=1024 in 32 chunks of 32 ----
// bf16 hi/lo split, mma.m16n8k16; staging via cp.async.bulk + mbarrier
// Weight blob columns PERMUTED: blob col (bx, wn_g, nf, c8) = logical col nf*1024 + bx*16 + wn_g*8 + c8
#define NCH   32
#define ACH_U 2048
#define BCH_U 1024
#define NSTAGE 4
#define STG_U (2*ACH_U + 2*BCH_U)
#define STG_BYTES (STG_U * 4)
#define SMEM_BYTES (1024 + NSTAGE * STG_BYTES)

// ---------------- persistent device scratch ----------------
__device__ float    g_h[B_ * H_];
__device__ float    g_c[B_ * H_];
__device__ int      g_tok[B_];
__device__ uint32_t g_A0H[B_ * H_ / 2];   // double-buffered A blobs
__device__ uint32_t g_A0L[B_ * H_ / 2];
__device__ uint32_t g_A1H[B_ * H_ / 2];
__device__ uint32_t g_A1L[B_ * H_ / 2];
__device__ uint32_t g_EH[V_ * H_ / 2];
__device__ uint32_t g_EL[V_ * H_ / 2];
__device__ uint32_t g_BeH[(size_t)N4H * H_ / 2];
__device__ uint32_t g_BeL[(size_t)N4H * H_ / 2];
__device__ uint32_t g_BdH[(size_t)N4H * H_ / 2];
__device__ uint32_t g_BdL[(size_t)N4H * H_ / 2];
__device__ uint32_t g_BwH[(size_t)N4H * H_ / 2];
__device__ uint32_t g_BwL[(size_t)N4H * H_ / 2];
__device__ float    g_encEW[V_ * N4H];    // tables in permuted (blob) column space
__device__ float    g_decEW[V_ * N4H];

// ---------------- helpers ----------------
__device__ __forceinline__ uint32_t packb(float lo_elem, float hi_elem) {
    __nv_bfloat162 t = __floats2bfloat162_rn(lo_elem, hi_elem);
    return *(uint32_t*)&t;
}
__device__ __forceinline__ void bsplit2(float x0, float x1, uint32_t& hi, uint32_t& lo) {
    __nv_bfloat16 b0 = __float2bfloat16(x0), b1 = __float2bfloat16(x1);
    float f0 = __bfloat162float(b0), f1 = __bfloat162float(b1);
    __nv_bfloat162 th; th.x = b0; th.y = b1;
    hi = *(uint32_t*)&th;
    lo = packb(x0 - f0, x1 - f1);
}

__device__ __forceinline__ void mma_bf16(float* d, const uint4& a, uint32_t b0, uint32_t b1) {
    asm volatile(
        "mma.sync.aligned.m16n8k16.row.col.f32.bf16.bf16.f32 "
        "{%0,%1,%2,%3}, {%4,%5,%6,%7}, {%8,%9}, {%0,%1,%2,%3};"
        : "+f"(d[0]), "+f"(d[1]), "+f"(d[2]), "+f"(d[3])
        : "r"(a.x), "r"(a.y), "r"(a.z), "r"(a.w), "r"(b0), "r"(b1));
}

__device__ __forceinline__ void mbar_init(uint32_t a, uint32_t cnt) {
    asm volatile("mbarrier.init.shared.b64 [%0], %1;" :: "r"(a), "r"(cnt) : "memory");
}
__device__ __forceinline__ void mbar_expect_tx(uint32_t a, uint32_t bytes) {
    asm volatile("mbarrier.arrive.expect_tx.shared.b64 _, [%0], %1;" :: "r"(a), "r"(bytes) : "memory");
}
__device__ __forceinline__ void mbar_wait(uint32_t a, uint32_t ph) {
    asm volatile(
        "{\n\t.reg .pred P;\n\t"
        "W%=:\n\t"
        "mbarrier.try_wait.parity.acquire.cta.shared::cta.b64 P, [%0], %1, 0x989680;\n\t"
        "@!P bra W%=;\n\t}"
        :: "r"(a), "r"(ph) : "memory");
}
__device__ __forceinline__ void bulk_cp(uint32_t dst, const void* src, uint32_t bytes, uint32_t mbar) {
    asm volatile(
        "cp.async.bulk.shared::cluster.global.mbarrier::complete_tx::bytes [%0], [%1], %2, [%3];"
        :: "r"(dst), "l"(src), "r"(bytes), "r"(mbar) : "memory");
}

__device__ __forceinline__ float sigf(float x) { return 1.0f / (1.0f + expf(-x)); }

// Write one (m, m+8) x (j0..j0+7) group into the bf16 A blob (used by emb/init path).
__device__ __forceinline__ void write_Ablob(uint32_t* AH, uint32_t* AL, int m, int j0,
                                            const float* r0, const float* r1)
{
    int tile = m >> 7, chunk = j0 >> 5, wm_g = (m & 127) >> 5;
    int ks = (j0 & 31) >> 4, half8 = (j0 & 15) >> 3;
    int mf = (m & 31) >> 4, gid = m & 7;
    size_t base = ((size_t)(tile * NCH + chunk)) * ACH_U + (size_t)(((wm_g * 2 + ks) * 2 + mf) * 128);
#pragma unroll
    for (int tig = 0; tig < 4; tig++) {
        int lane = gid * 4 + tig;
        uint32_t pH0, pL0, pH1, pL1;
        bsplit2(r0[2 * tig], r0[2 * tig + 1], pH0, pL0);
        bsplit2(r1[2 * tig], r1[2 * tig + 1], pH1, pL1);
        uint2 vh; vh.x = pH0; vh.y = pH1;
        uint2 vl; vl.x = pL0; vl.y = pL1;
        *(uint2*)(AH + base + lane * 4 + half8 * 2) = vh;
        *(uint2*)(AL + base + lane * 4 + half8 * 2) = vl;
    }
}

// ---------------- weight split (PERMUTED columns): W[1024][4096] -> bf16 B blob ----------------
// blockIdx.x in [0,128): bx = >>1, wg = &1. Local col tx -> logical col (tx>>3)*1024 + bx*16 + wg*8 + (tx&7)
__global__ void split_weightB(const float* __restrict__ W,
                              uint32_t* __restrict__ BH, uint32_t* __restrict__ BL)
{
    __shared__ float sH[32][33];
    __shared__ float sL[32][33];
    int bx = blockIdx.x >> 1, wg = blockIdx.x & 1;
    int k0 = blockIdx.y * 32;
    int tx = threadIdx.x & 31, ty = threadIdx.x >> 5;
    int lcol = (tx >> 3) * 1024 + bx * 16 + wg * 8 + (tx & 7);
#pragma unroll
    for (int i = 0; i < 4; i++) {
        int k = ty + i * 8;
        float x = W[(size_t)(k0 + k) * N4H + lcol];
        __nv_bfloat16 bh = __float2bfloat16(x);
        float hf = __bfloat162float(bh);
        sH[k][tx] = hf;
        sL[k][tx] = __bfloat162float(__float2bfloat16(x - hf));
    }
    __syncthreads();
    int ks   = threadIdx.x >> 7;
    int lane = (threadIdx.x >> 2) & 31;
    int q    = threadIdx.x & 3;
    int gid = lane >> 2, tig = lane & 3;
    int ncol = q * 8 + gid;
    int kb = ks * 16 + 2 * tig;
    uint32_t b0H = packb(sH[kb][ncol],     sH[kb + 1][ncol]);
    uint32_t b1H = packb(sH[kb + 8][ncol], sH[kb + 9][ncol]);
    uint32_t b0L = packb(sL[kb][ncol],     sL[kb + 1][ncol]);
    uint32_t b1L = packb(sL[kb + 8][ncol], sL[kb + 9][ncol]);
    int chunk = k0 >> 5;
    size_t ob = ((size_t)(bx * NCH + chunk)) * BCH_U + wg * 512 + ks * 256 + lane * 8 + q * 2;
    uint2 vh; vh.x = b0H; vh.y = b1H;
    uint2 vl; vl.x = b0L; vl.y = b1L;
    *(uint2*)(BH + ob) = vh;
    *(uint2*)(BL + ob) = vl;
}

// ---------------- emb -> A blob (128 rows, tile 0) ----------------
__global__ void emb_blob(const float* __restrict__ emb,
                         uint32_t* __restrict__ AH, uint32_t* __restrict__ AL)
{
    int t = blockIdx.x * 256 + threadIdx.x;
    if (t >= 8192) return;
    int mp = t >> 7;
    int m  = ((mp >> 3) << 4) | (mp & 7);
    int j0 = (t & 127) << 3;
    float r0[8], r1[8];
    const float* p0 = emb + (size_t)m * H_ + j0;
    const float* p1 = emb + (size_t)(m + 8) * H_ + j0;
#pragma unroll
    for (int i = 0; i < 8; i++) { r0[i] = p0[i]; r1[i] = p1[i]; }
    write_Ablob(AH, AL, m, j0, r0, r1);
}

// ---------------- fused GEMM + LSTM cell (bf16 split, bulk staging) ----------------
// maskSrc==null : table-build mode -> Z[m][blob-col] = acc + bias[logical col]
// maskSrc!=null : fused mode -> gates from acc+addTbl, cell update, h/c store, blob emit
__global__ __launch_bounds__(256)
void gemm_tc(const uint32_t* __restrict__ AH, const uint32_t* __restrict__ AL,
             const uint32_t* __restrict__ BH, const uint32_t* __restrict__ BL,
             const float* __restrict__ bias,
             const float* __restrict__ addTbl, const int* __restrict__ addIdx, int idxStride,
             const int* __restrict__ maskSrc, int maskStride,
             float* __restrict__ h, float* __restrict__ c,
             uint32_t* __restrict__ oAH, uint32_t* __restrict__ oAL,
             float* __restrict__ Z)
{
    extern __shared__ uint32_t smu[];
    const int tid = threadIdx.x;
    const int wid = tid >> 5;
    const int lid = tid & 31;
    const int gid = lid >> 2;
    const int tig = lid & 3;
    const int bn  = blockIdx.x * 64;
    const int bm  = blockIdx.y * 128;
    const int wm_g = wid & 3;
    const int wn_g = wid >> 2;

    const uint32_t* AHt = AH + (size_t)blockIdx.y * NCH * ACH_U;
    const uint32_t* ALt = AL + (size_t)blockIdx.y * NCH * ACH_U;
    const uint32_t* BHt = BH + (size_t)blockIdx.x * NCH * BCH_U;
    const uint32_t* BLt = BL + (size_t)blockIdx.x * NCH * BCH_U;

    const uint32_t smb = (uint32_t)__cvta_generic_to_shared(smu);
    const uint32_t mb_base  = smb;
    const uint32_t dat_base = smb + 1024;

    if (tid == 0) {
#pragma unroll
        for (int s = 0; s < NSTAGE; s++) mbar_init(mb_base + s * 8, 1);
        asm volatile("fence.proxy.async.shared::cta;" ::: "memory");
    }
    __syncthreads();

    auto issue = [&](int cc) {
        if (tid != 0) return;
        int s = cc & 3;
        uint32_t mb = mb_base + s * 8;
        uint32_t d  = dat_base + s * STG_BYTES;
        mbar_expect_tx(mb, STG_BYTES);
        bulk_cp(d,                  AHt + (size_t)cc * ACH_U, ACH_U * 4, mb);
        bulk_cp(d + ACH_U * 4,      ALt + (size_t)cc * ACH_U, ACH_U * 4, mb);
        bulk_cp(d + 2 * ACH_U * 4,  BHt + (size_t)cc * BCH_U, BCH_U * 4, mb);
        bulk_cp(d + 2 * ACH_U * 4 + BCH_U * 4, BLt + (size_t)cc * BCH_U, BCH_U * 4, mb);
    };

    float acc[2][4][4];
#pragma unroll
    for (int mf = 0; mf < 2; mf++)
#pragma unroll
        for (int nf = 0; nf < 4; nf++)
#pragma unroll
            for (int q = 0; q < 4; q++) acc[mf][nf][q] = 0.f;

    issue(0); issue(1); issue(2);

    for (int cch = 0; cch < NCH; cch++) {
        const int s = cch & 3;
        mbar_wait(mb_base + s * 8, (cch >> 2) & 1);

        const uint32_t* sAH = smu + 256 + s * STG_U;
        const uint32_t* sAL = sAH + ACH_U;
        const uint32_t* sBH = sAL + ACH_U;
        const uint32_t* sBL = sBH + BCH_U;

#pragma unroll
        for (int ks = 0; ks < 2; ks++) {
            uint4 aH0 = *(const uint4*)(sAH + ((wm_g * 2 + ks) * 2 + 0) * 128 + lid * 4);
            uint4 aH1 = *(const uint4*)(sAH + ((wm_g * 2 + ks) * 2 + 1) * 128 + lid * 4);
            uint4 aL0 = *(const uint4*)(sAL + ((wm_g * 2 + ks) * 2 + 0) * 128 + lid * 4);
            uint4 aL1 = *(const uint4*)(sAL + ((wm_g * 2 + ks) * 2 + 1) * 128 + lid * 4);
            uint4 bh0 = *(const uint4*)(sBH + (wn_g * 2 + ks) * 256 + lid * 8);
            uint4 bh1 = *(const uint4*)(sBH + (wn_g * 2 + ks) * 256 + lid * 8 + 4);
            uint4 bl0 = *(const uint4*)(sBL + (wn_g * 2 + ks) * 256 + lid * 8);
            uint4 bl1 = *(const uint4*)(sBL + (wn_g * 2 + ks) * 256 + lid * 8 + 4);
            uint32_t bHf[4][2] = {{bh0.x, bh0.y}, {bh0.z, bh0.w}, {bh1.x, bh1.y}, {bh1.z, bh1.w}};
            uint32_t bLf[4][2] = {{bl0.x, bl0.y}, {bl0.z, bl0.w}, {bl1.x, bl1.y}, {bl1.z, bl1.w}};
#pragma unroll
            for (int nf = 0; nf < 4; nf++) {
                mma_bf16(acc[0][nf], aH0, bHf[nf][0], bHf[nf][1]);
                mma_bf16(acc[1][nf], aH1, bHf[nf][0], bHf[nf][1]);
            }
#pragma unroll
            for (int nf = 0; nf < 4; nf++) {
                mma_bf16(acc[0][nf], aH0, bLf[nf][0], bLf[nf][1]);
                mma_bf16(acc[1][nf], aH1, bLf[nf][0], bLf[nf][1]);
            }
#pragma unroll
            for (int nf = 0; nf < 4; nf++) {
                mma_bf16(acc[0][nf], aL0, bHf[nf][0], bHf[nf][1]);
                mma_bf16(acc[1][nf], aL1, bHf[nf][0], bHf[nf][1]);
            }
        }
        __syncthreads();
        if (cch + 3 < NCH) issue(cch + 3);
    }

    if (maskSrc == nullptr) {
        // ---- table-build epilogue: Z in blob-column space, bias at logical col ----
#pragma unroll
        for (int mf = 0; mf < 2; mf++) {
#pragma unroll
            for (int half = 0; half < 2; half++) {
                int m = bm + wm_g * 32 + mf * 16 + half * 8 + gid;
                float* zrow = Z + (size_t)m * N4H;
#pragma unroll
                for (int nf = 0; nf < 4; nf++) {
                    int cn = bn + wn_g * 32 + nf * 8 + tig * 2;
                    float v0 = acc[mf][nf][half * 2 + 0];
                    float v1 = acc[mf][nf][half * 2 + 1];
                    if (bias) {
                        int lc = nf * 1024 + (bn >> 2) + wn_g * 8 + tig * 2;
                        v0 += bias[lc]; v1 += bias[lc + 1];
                    }
                    float2 o; o.x = v0; o.y = v1;
                    *(float2*)(zrow + cn) = o;
                }
            }
        }
        return;
    }

    // ---- fused LSTM-cell epilogue ----
    const int jb = blockIdx.x * 16 + wn_g * 8 + tig * 2;   // j0; j1 = jb+1
    const int chunk = blockIdx.x >> 1;
    const int ksb   = blockIdx.x & 1;
#pragma unroll
    for (int mf = 0; mf < 2; mf++) {
        float hv[2][2];
#pragma unroll
        for (int half = 0; half < 2; half++) {
            int m = bm + wm_g * 32 + mf * 16 + half * 8 + gid;
            bool act = maskSrc[(size_t)m * maskStride] != 0;
            float* hrow = h + (size_t)m * H_ + jb;
            if (act) {
                const float* arow = addTbl + (size_t)addIdx[(size_t)m * idxStride] * N4H
                                   + bn + wn_g * 32 + tig * 2;
                float* crow = c + (size_t)m * H_ + jb;
#pragma unroll
                for (int e = 0; e < 2; e++) {
                    int q = half * 2 + e;
                    float vi = acc[mf][0][q] + arow[e];
                    float vf = acc[mf][1][q] + arow[8 + e];
                    float vg = acc[mf][2][q] + arow[16 + e];
                    float vo = acc[mf][3][q] + arow[24 + e];
                    float c2 = sigf(vf) * crow[e] + sigf(vi) * tanhf(vg);
                    float h2 = sigf(vo) * tanhf(c2);
                    crow[e] = c2;
                    hrow[e] = h2;
                    hv[half][e] = h2;
                }
            } else {
                hv[half][0] = hrow[0];
                hv[half][1] = hrow[1];
            }
        }
        // blob emit (always — keeps double-buffered blob coherent)
        uint32_t pH0, pL0, pH1, pL1;
        bsplit2(hv[0][0], hv[0][1], pH0, pL0);
        bsplit2(hv[1][0], hv[1][1], pH1, pL1);
        size_t base = ((size_t)(blockIdx.y * NCH + chunk)) * ACH_U
                    + (size_t)(((wm_g * 2 + ksb) * 2 + mf) * 128)
                    + (gid * 4 + tig) * 4 + wn_g * 2;
        uint2 vh; vh.x = pH0; vh.y = pH1;
        uint2 vl; vl.x = pL0; vl.y = pL1;
        *(uint2*)(oAH + base) = vh;
        *(uint2*)(oAL + base) = vl;
    }
}

// ---------------- decoder output: logits + softmax + argmax ----------------
__global__ void dec_output(const float* __restrict__ h,
                           const float* __restrict__ outW, const float* __restrict__ outb,
                           float* __restrict__ out, int l,
                           int* __restrict__ tok, float* __restrict__ tokOut)
{
    const int ROWS = 4;
    __shared__ float hs[ROWS][H_];
    __shared__ float red[V_];
    __shared__ float smax, ssum;
    __shared__ int   sarg;

    int m0 = blockIdx.x * ROWS;
    int v  = threadIdx.x;

    for (int idx = threadIdx.x; idx < ROWS * H_; idx += blockDim.x) {
        int r = idx >> 10;
        hs[r][idx & 1023] = h[(size_t)(m0 + r) * H_ + (idx & 1023)];
    }
    __syncthreads();

    float acc[ROWS] = {0.f, 0.f, 0.f, 0.f};
#pragma unroll 8
    for (int k = 0; k < H_; k++) {
        float w = outW[(size_t)k * V_ + v];
#pragma unroll
        for (int r = 0; r < ROWS; r++) acc[r] += hs[r][k] * w;
    }
    float bb = outb[v];

    for (int r = 0; r < ROWS; r++) {
        float logit = acc[r] + bb;
        red[v] = logit;
        __syncthreads();
        if (v == 0) {
            float mx = red[0]; int am = 0;
            for (int q = 1; q < V_; q++) if (red[q] > mx) { mx = red[q]; am = q; }
            smax = mx; sarg = am;
        }
        __syncthreads();
        float e = expf(logit - smax);
        red[v] = e;
        __syncthreads();
        if (v == 0) {
            float s = 0.f;
            for (int q = 0; q < V_; q++) s += red[q];
            ssum = s;
        }
        __syncthreads();
        int m = m0 + r;
        out[(size_t)m * (L_ * V_) + (size_t)l * V_ + v] = e / ssum;
        if (v == 0) {
            tok[m] = sarg;
            if (tokOut) tokOut[(size_t)l * B_ + m] = (float)sarg;
        }
        __syncthreads();
    }
}

// ---------------- init ----------------
__global__ void init_state(float* __restrict__ h, float* __restrict__ c,
                           uint32_t* __restrict__ AH, uint32_t* __restrict__ AL,
                           int* __restrict__ tok)
{
    int i = blockIdx.x * blockDim.x + threadIdx.x;
    if (i < B_ * H_) { h[i] = 0.f; c[i] = 0.f; }
    if (i < B_ * H_ / 2) { AH[i] = 0u; AL[i] = 0u; }
    if (i < B_) tok[i] = V_ - 1;
}

// ---------------- launch ----------------
extern "C" void kernel_launch(void* const* d_in, const int* in_sizes, int n_in,
                              void* d_out, int out_size)
{
    int base = 1;
    if (n_in >= 12 && in_sizes[1] == 1) base = 2;

    const int*   inputs  = (const int*)  d_in[0];
    const float* enc_emb = (const float*)d_in[base + 0];
    const float* enc_W   = (const float*)d_in[base + 1];
    const float* enc_U   = (const float*)d_in[base + 2];
    const float* enc_b   = (const float*)d_in[base + 3];
    const float* dec_emb = (const float*)d_in[base + 4];
    const float* dec_W   = (const float*)d_in[base + 5];
    const float* dec_U   = (const float*)d_in[base + 6];
    const float* dec_b   = (const float*)d_in[base + 7];
    const float* out_W   = (const float*)d_in[base + 8];
    const float* out_b   = (const float*)d_in[base + 9];
    float* out = (float*)d_out;

    float *p_h, *p_c, *p_encEW, *p_decEW;
    uint32_t *pA_H[2], *pA_L[2], *p_EH, *p_EL, *p_BeH, *p_BeL, *p_BdH, *p_BdL, *p_BwH, *p_BwL;
    int* p_tok;
    cudaGetSymbolAddress((void**)&p_h, g_h);
    cudaGetSymbolAddress((void**)&p_c, g_c);
    cudaGetSymbolAddress((void**)&p_tok, g_tok);
    cudaGetSymbolAddress((void**)&pA_H[0], g_A0H);
    cudaGetSymbolAddress((void**)&pA_L[0], g_A0L);
    cudaGetSymbolAddress((void**)&pA_H[1], g_A1H);
    cudaGetSymbolAddress((void**)&pA_L[1], g_A1L);
    cudaGetSymbolAddress((void**)&p_EH, g_EH);
    cudaGetSymbolAddress((void**)&p_EL, g_EL);
    cudaGetSymbolAddress((void**)&p_BeH, g_BeH);
    cudaGetSymbolAddress((void**)&p_BeL, g_BeL);
    cudaGetSymbolAddress((void**)&p_BdH, g_BdH);
    cudaGetSymbolAddress((void**)&p_BdL, g_BdL);
    cudaGetSymbolAddress((void**)&p_BwH, g_BwH);
    cudaGetSymbolAddress((void**)&p_BwL, g_BwL);
    cudaGetSymbolAddress((void**)&p_encEW, g_encEW);
    cudaGetSymbolAddress((void**)&p_decEW, g_decEW);

    float* tokOut = nullptr;
    if (out_size >= B_ * L_ * V_ + L_ * B_) tokOut = out + (size_t)B_ * L_ * V_;

    cudaFuncSetAttribute(gemm_tc, cudaFuncAttributeMaxDynamicSharedMemorySize, SMEM_BYTES);

    init_state<<<(B_ * H_ + 255) / 256, 256>>>(p_h, p_c, pA_H[0], pA_L[0], p_tok);

    dim3 wg(128, H_ / 32);

    // ---- table builds (tables live in permuted/blob column space; bias folded) ----
    split_weightB<<<wg, 256>>>(enc_W, p_BwH, p_BwL);
    emb_blob<<<32, 256>>>(enc_emb, p_EH, p_EL);
    gemm_tc<<<dim3(64, 1), 256, SMEM_BYTES>>>(p_EH, p_EL, p_BwH, p_BwL,
                                              enc_b, nullptr, nullptr, 0,
                                              nullptr, 0, nullptr, nullptr, nullptr, nullptr,
                                              p_encEW);
    split_weightB<<<wg, 256>>>(dec_W, p_BwH, p_BwL);
    emb_blob<<<32, 256>>>(dec_emb, p_EH, p_EL);
    gemm_tc<<<dim3(64, 1), 256, SMEM_BYTES>>>(p_EH, p_EL, p_BwH, p_BwL,
                                              dec_b, nullptr, nullptr, 0,
                                              nullptr, 0, nullptr, nullptr, nullptr, nullptr,
                                              p_decEW);
    split_weightB<<<wg, 256>>>(enc_U, p_BeH, p_BeL);
    split_weightB<<<wg, 256>>>(dec_U, p_BdH, p_BdL);

    dim3 gstep(64, 2);   // 128 CTAs
    int pb = 0;          // current A blob parity

    // ---- encoder (fused gemm+cell) ----
    for (int t = 0; t < T_; t++) {
        gemm_tc<<<gstep, 256, SMEM_BYTES>>>(pA_H[pb], pA_L[pb], p_BeH, p_BeL,
                                            nullptr, p_encEW, inputs + t, T_,
                                            inputs + t, T_, p_h, p_c,
                                            pA_H[pb ^ 1], pA_L[pb ^ 1], nullptr);
        pb ^= 1;
    }

    // ---- decoder (fused gemm+cell + output) ----
    for (int l = 0; l < L_; l++) {
        gemm_tc<<<gstep, 256, SMEM_BYTES>>>(pA_H[pb], pA_L[pb], p_BdH, p_BdL,
                                            nullptr, p_decEW, p_tok, 1,
                                            p_tok, 1, p_h, p_c,
                                            pA_H[pb ^ 1], pA_L[pb ^ 1], nullptr);
        pb ^= 1;
        dec_output<<<B_ / 4, V_>>>(p_h, out_W, out_b, out, l, p_tok, tokOut);
    }
}

// round 14
// speedup vs baseline: 1.5603x; 1.0966x over previous
#include <cuda_runtime.h>
#include <cuda_bf16.h>
#include <math.h>
#include <stdint.h>

#define B_   256
#define T_   64
#define H_   1024
#define V_   128
#define L_   32
#define N4H  4096

#define NCH   32
#define ACH_U 2048
#define BCH_U 1024
#define NSTAGE 4
#define STG_U (2*ACH_U + 2*BCH_U)
#define STG_BYTES (STG_U * 4)
#define SMEM_BYTES (1024 + NSTAGE * STG_BYTES)
#define NCTA 128

// ---------------- persistent device scratch ----------------
__device__ float    g_h[B_ * H_];
__device__ float    g_c[B_ * H_];
__device__ int      g_tok[B_];
__device__ uint32_t g_A0H[B_ * H_ / 2];
__device__ uint32_t g_A0L[B_ * H_ / 2];
__device__ uint32_t g_A1H[B_ * H_ / 2];
__device__ uint32_t g_A1L[B_ * H_ / 2];
__device__ uint32_t g_EH[V_ * H_ / 2];
__device__ uint32_t g_EL[V_ * H_ / 2];
__device__ uint32_t g_BeH[(size_t)N4H * H_ / 2];
__device__ uint32_t g_BeL[(size_t)N4H * H_ / 2];
__device__ uint32_t g_BdH[(size_t)N4H * H_ / 2];
__device__ uint32_t g_BdL[(size_t)N4H * H_ / 2];
__device__ uint32_t g_BwH[(size_t)N4H * H_ / 2];
__device__ uint32_t g_BwL[(size_t)N4H * H_ / 2];
__device__ float    g_encEW[V_ * N4H];
__device__ float    g_decEW[V_ * N4H];
// grid barrier state
__device__ unsigned g_barCnt = 0;
__device__ volatile unsigned g_barGen = 0;

// ---------------- helpers ----------------
__device__ __forceinline__ uint32_t packb(float lo_elem, float hi_elem) {
    __nv_bfloat162 t = __floats2bfloat162_rn(lo_elem, hi_elem);
    return *(uint32_t*)&t;
}
__device__ __forceinline__ void bsplit2(float x0, float x1, uint32_t& hi, uint32_t& lo) {
    __nv_bfloat16 b0 = __float2bfloat16(x0), b1 = __float2bfloat16(x1);
    float f0 = __bfloat162float(b0), f1 = __bfloat162float(b1);
    __nv_bfloat162 th; th.x = b0; th.y = b1;
    hi = *(uint32_t*)&th;
    lo = packb(x0 - f0, x1 - f1);
}
__device__ __forceinline__ void mma_bf16(float* d, const uint4& a, uint32_t b0, uint32_t b1) {
    asm volatile(
        "mma.sync.aligned.m16n8k16.row.col.f32.bf16.bf16.f32 "
        "{%0,%1,%2,%3}, {%4,%5,%6,%7}, {%8,%9}, {%0,%1,%2,%3};"
        : "+f"(d[0]), "+f"(d[1]), "+f"(d[2]), "+f"(d[3])
        : "r"(a.x), "r"(a.y), "r"(a.z), "r"(a.w), "r"(b0), "r"(b1));
}
__device__ __forceinline__ void mbar_init(uint32_t a, uint32_t cnt) {
    asm volatile("mbarrier.init.shared.b64 [%0], %1;" :: "r"(a), "r"(cnt) : "memory");
}
__device__ __forceinline__ void mbar_expect_tx(uint32_t a, uint32_t bytes) {
    asm volatile("mbarrier.arrive.expect_tx.shared.b64 _, [%0], %1;" :: "r"(a), "r"(bytes) : "memory");
}
__device__ __forceinline__ void mbar_wait(uint32_t a, uint32_t ph) {
    asm volatile(
        "{\n\t.reg .pred P;\n\t"
        "W%=:\n\t"
        "mbarrier.try_wait.parity.acquire.cta.shared::cta.b64 P, [%0], %1, 0x989680;\n\t"
        "@!P bra W%=;\n\t}"
        :: "r"(a), "r"(ph) : "memory");
}
__device__ __forceinline__ void bulk_cp(uint32_t dst, const void* src, uint32_t bytes, uint32_t mbar) {
    asm volatile(
        "cp.async.bulk.shared::cluster.global.mbarrier::complete_tx::bytes [%0], [%1], %2, [%3];"
        :: "r"(dst), "l"(src), "r"(bytes), "r"(mbar) : "memory");
}
__device__ __forceinline__ float sigf(float x) { return 1.0f / (1.0f + expf(-x)); }

__device__ __forceinline__ void grid_bar() {
    __threadfence();
    __syncthreads();
    if (threadIdx.x == 0) {
        unsigned gen = g_barGen;
        if (atomicAdd(&g_barCnt, 1u) == NCTA - 1u) {
            g_barCnt = 0;
            __threadfence();
            g_barGen = gen + 1;
        } else {
            while (g_barGen == gen) {}
        }
    }
    __syncthreads();
    __threadfence();
}

// Write one (m, m+8) x (j0..j0+7) group into the bf16 A blob (emb path).
__device__ __forceinline__ void write_Ablob(uint32_t* AH, uint32_t* AL, int m, int j0,
                                            const float* r0, const float* r1)
{
    int tile = m >> 7, chunk = j0 >> 5, wm_g = (m & 127) >> 5;
    int ks = (j0 & 31) >> 4, half8 = (j0 & 15) >> 3;
    int mf = (m & 31) >> 4, gid = m & 7;
    size_t base = ((size_t)(tile * NCH + chunk)) * ACH_U + (size_t)(((wm_g * 2 + ks) * 2 + mf) * 128);
#pragma unroll
    for (int tig = 0; tig < 4; tig++) {
        int lane = gid * 4 + tig;
        uint32_t pH0, pL0, pH1, pL1;
        bsplit2(r0[2 * tig], r0[2 * tig + 1], pH0, pL0);
        bsplit2(r1[2 * tig], r1[2 * tig + 1], pH1, pL1);
        uint2 vh; vh.x = pH0; vh.y = pH1;
        uint2 vl; vl.x = pL0; vl.y = pL1;
        *(uint2*)(AH + base + lane * 4 + half8 * 2) = vh;
        *(uint2*)(AL + base + lane * 4 + half8 * 2) = vl;
    }
}

// ---------------- weight split (PERMUTED columns) ----------------
__global__ void split_weightB(const float* __restrict__ W,
                              uint32_t* __restrict__ BH, uint32_t* __restrict__ BL)
{
    __shared__ float sH[32][33];
    __shared__ float sL[32][33];
    int bx = blockIdx.x >> 1, wg = blockIdx.x & 1;
    int k0 = blockIdx.y * 32;
    int tx = threadIdx.x & 31, ty = threadIdx.x >> 5;
    int lcol = (tx >> 3) * 1024 + bx * 16 + wg * 8 + (tx & 7);
#pragma unroll
    for (int i = 0; i < 4; i++) {
        int k = ty + i * 8;
        float x = W[(size_t)(k0 + k) * N4H + lcol];
        __nv_bfloat16 bh = __float2bfloat16(x);
        float hf = __bfloat162float(bh);
        sH[k][tx] = hf;
        sL[k][tx] = __bfloat162float(__float2bfloat16(x - hf));
    }
    __syncthreads();
    int ks   = threadIdx.x >> 7;
    int lane = (threadIdx.x >> 2) & 31;
    int q    = threadIdx.x & 3;
    int gid = lane >> 2, tig = lane & 3;
    int ncol = q * 8 + gid;
    int kb = ks * 16 + 2 * tig;
    uint32_t b0H = packb(sH[kb][ncol],     sH[kb + 1][ncol]);
    uint32_t b1H = packb(sH[kb + 8][ncol], sH[kb + 9][ncol]);
    uint32_t b0L = packb(sL[kb][ncol],     sL[kb + 1][ncol]);
    uint32_t b1L = packb(sL[kb + 8][ncol], sL[kb + 9][ncol]);
    int chunk = k0 >> 5;
    size_t ob = ((size_t)(bx * NCH + chunk)) * BCH_U + wg * 512 + ks * 256 + lane * 8 + q * 2;
    uint2 vh; vh.x = b0H; vh.y = b1H;
    uint2 vl; vl.x = b0L; vl.y = b1L;
    *(uint2*)(BH + ob) = vh;
    *(uint2*)(BL + ob) = vl;
}

// ---------------- emb -> A blob ----------------
__global__ void emb_blob(const float* __restrict__ emb,
                         uint32_t* __restrict__ AH, uint32_t* __restrict__ AL)
{
    int t = blockIdx.x * 256 + threadIdx.x;
    if (t >= 8192) return;
    int mp = t >> 7;
    int m  = ((mp >> 3) << 4) | (mp & 7);
    int j0 = (t & 127) << 3;
    float r0[8], r1[8];
    const float* p0 = emb + (size_t)m * H_ + j0;
    const float* p1 = emb + (size_t)(m + 8) * H_ + j0;
#pragma unroll
    for (int i = 0; i < 8; i++) { r0[i] = p0[i]; r1[i] = p1[i]; }
    write_Ablob(AH, AL, m, j0, r0, r1);
}

// ---------------- table-build GEMM (blob-col output, bias at logical col) ----------------
__global__ __launch_bounds__(256)
void gemm_table(const uint32_t* __restrict__ AH, const uint32_t* __restrict__ AL,
                const uint32_t* __restrict__ BH, const uint32_t* __restrict__ BL,
                const float* __restrict__ bias, float* __restrict__ Z)
{
    extern __shared__ uint32_t smu[];
    const int tid = threadIdx.x;
    const int wid = tid >> 5;
    const int lid = tid & 31;
    const int gid = lid >> 2;
    const int tig = lid & 3;
    const int bn  = blockIdx.x * 64;
    const int wm_g = wid & 3;
    const int wn_g = wid >> 2;

    const uint32_t* BHt = BH + (size_t)blockIdx.x * NCH * BCH_U;
    const uint32_t* BLt = BL + (size_t)blockIdx.x * NCH * BCH_U;

    const uint32_t smb = (uint32_t)__cvta_generic_to_shared(smu);
    if (tid == 0) {
#pragma unroll
        for (int s = 0; s < NSTAGE; s++) mbar_init(smb + s * 8, 1);
        asm volatile("fence.proxy.async.shared::cta;" ::: "memory");
    }
    __syncthreads();

    auto issue = [&](int cc) {
        if (tid != 0) return;
        int s = cc & 3;
        uint32_t mb = smb + s * 8;
        uint32_t d  = smb + 1024 + s * STG_BYTES;
        mbar_expect_tx(mb, STG_BYTES);
        bulk_cp(d,                  AH + (size_t)cc * ACH_U, ACH_U * 4, mb);
        bulk_cp(d + ACH_U * 4,      AL + (size_t)cc * ACH_U, ACH_U * 4, mb);
        bulk_cp(d + 2 * ACH_U * 4,  BHt + (size_t)cc * BCH_U, BCH_U * 4, mb);
        bulk_cp(d + 2 * ACH_U * 4 + BCH_U * 4, BLt + (size_t)cc * BCH_U, BCH_U * 4, mb);
    };

    float acc[2][4][4];
#pragma unroll
    for (int mf = 0; mf < 2; mf++)
#pragma unroll
        for (int nf = 0; nf < 4; nf++)
#pragma unroll
            for (int q = 0; q < 4; q++) acc[mf][nf][q] = 0.f;

    issue(0); issue(1); issue(2);

    for (int cch = 0; cch < NCH; cch++) {
        const int s = cch & 3;
        mbar_wait(smb + s * 8, (cch >> 2) & 1);
        const uint32_t* sAH = smu + 256 + s * STG_U;
        const uint32_t* sAL = sAH + ACH_U;
        const uint32_t* sBH = sAL + ACH_U;
        const uint32_t* sBL = sBH + BCH_U;
#pragma unroll
        for (int ks = 0; ks < 2; ks++) {
            uint4 aH0 = *(const uint4*)(sAH + ((wm_g * 2 + ks) * 2 + 0) * 128 + lid * 4);
            uint4 aH1 = *(const uint4*)(sAH + ((wm_g * 2 + ks) * 2 + 1) * 128 + lid * 4);
            uint4 aL0 = *(const uint4*)(sAL + ((wm_g * 2 + ks) * 2 + 0) * 128 + lid * 4);
            uint4 aL1 = *(const uint4*)(sAL + ((wm_g * 2 + ks) * 2 + 1) * 128 + lid * 4);
            uint4 bh0 = *(const uint4*)(sBH + (wn_g * 2 + ks) * 256 + lid * 8);
            uint4 bh1 = *(const uint4*)(sBH + (wn_g * 2 + ks) * 256 + lid * 8 + 4);
            uint4 bl0 = *(const uint4*)(sBL + (wn_g * 2 + ks) * 256 + lid * 8);
            uint4 bl1 = *(const uint4*)(sBL + (wn_g * 2 + ks) * 256 + lid * 8 + 4);
            uint32_t bHf[4][2] = {{bh0.x, bh0.y}, {bh0.z, bh0.w}, {bh1.x, bh1.y}, {bh1.z, bh1.w}};
            uint32_t bLf[4][2] = {{bl0.x, bl0.y}, {bl0.z, bl0.w}, {bl1.x, bl1.y}, {bl1.z, bl1.w}};
#pragma unroll
            for (int nf = 0; nf < 4; nf++) {
                mma_bf16(acc[0][nf], aH0, bHf[nf][0], bHf[nf][1]);
                mma_bf16(acc[1][nf], aH1, bHf[nf][0], bHf[nf][1]);
            }
#pragma unroll
            for (int nf = 0; nf < 4; nf++) {
                mma_bf16(acc[0][nf], aH0, bLf[nf][0], bLf[nf][1]);
                mma_bf16(acc[1][nf], aH1, bLf[nf][0], bLf[nf][1]);
            }
#pragma unroll
            for (int nf = 0; nf < 4; nf++) {
                mma_bf16(acc[0][nf], aL0, bHf[nf][0], bHf[nf][1]);
                mma_bf16(acc[1][nf], aL1, bHf[nf][0], bHf[nf][1]);
            }
        }
        __syncthreads();
        if (cch + 3 < NCH) issue(cch + 3);
    }

#pragma unroll
    for (int mf = 0; mf < 2; mf++) {
#pragma unroll
        for (int half = 0; half < 2; half++) {
            int m = wm_g * 32 + mf * 16 + half * 8 + gid;
            float* zrow = Z + (size_t)m * N4H;
#pragma unroll
            for (int nf = 0; nf < 4; nf++) {
                int cn = bn + wn_g * 32 + nf * 8 + tig * 2;
                float v0 = acc[mf][nf][half * 2 + 0];
                float v1 = acc[mf][nf][half * 2 + 1];
                int lc = nf * 1024 + (bn >> 2) + wn_g * 8 + tig * 2;
                v0 += bias[lc]; v1 += bias[lc + 1];
                float2 o; o.x = v0; o.y = v1;
                *(float2*)(zrow + cn) = o;
            }
        }
    }
}

// ---------------- persistent fused kernel: all 96 steps + decoder output ----------------
__global__ __launch_bounds__(256, 1)
void lstm_persist(const int* __restrict__ inputs,
                  const uint32_t* __restrict__ BeH, const uint32_t* __restrict__ BeL,
                  const uint32_t* __restrict__ BdH, const uint32_t* __restrict__ BdL,
                  const float* __restrict__ encEW, const float* __restrict__ decEW,
                  float* __restrict__ h, float* __restrict__ c, int* __restrict__ tok,
                  uint32_t* __restrict__ A0H, uint32_t* __restrict__ A0L,
                  uint32_t* __restrict__ A1H, uint32_t* __restrict__ A1L,
                  const float* __restrict__ outW, const float* __restrict__ outb,
                  float* __restrict__ out, float* __restrict__ tokOut)
{
    extern __shared__ uint32_t smu[];
    const int tid = threadIdx.x;
    const int wid = tid >> 5;
    const int lid = tid & 31;
    const int gid = lid >> 2;
    const int tig = lid & 3;
    const int bn  = blockIdx.x * 64;
    const int bm  = blockIdx.y * 128;
    const int wm_g = wid & 3;
    const int wn_g = wid >> 2;
    const int linear = blockIdx.y * 64 + blockIdx.x;

    const uint32_t smb = (uint32_t)__cvta_generic_to_shared(smu);
    if (tid == 0) {
#pragma unroll
        for (int s = 0; s < NSTAGE; s++) mbar_init(smb + s * 8, 1);
        asm volatile("fence.proxy.async.shared::cta;" ::: "memory");
    }
    __syncthreads();

    const size_t yoff = (size_t)blockIdx.y * NCH * ACH_U;
    const size_t xoff = (size_t)blockIdx.x * NCH * BCH_U;
    int pb = 0;

    for (int step = 0; step < T_ + L_; step++) {
        const bool isEnc = step < T_;
        const uint32_t* AHt = (pb ? A1H : A0H) + yoff;
        const uint32_t* ALt = (pb ? A1L : A0L) + yoff;
        const uint32_t* BHt = (isEnc ? BeH : BdH) + xoff;
        const uint32_t* BLt = (isEnc ? BeL : BdL) + xoff;
        const float* tbl = isEnc ? encEW : decEW;
        uint32_t* oAH = (pb ? A0H : A1H);
        uint32_t* oAL = (pb ? A0L : A1L);

        auto issue = [&](int cc) {
            if (tid != 0) return;
            int s = cc & 3;
            uint32_t mb = smb + s * 8;
            uint32_t d  = smb + 1024 + s * STG_BYTES;
            mbar_expect_tx(mb, STG_BYTES);
            bulk_cp(d,                  AHt + (size_t)cc * ACH_U, ACH_U * 4, mb);
            bulk_cp(d + ACH_U * 4,      ALt + (size_t)cc * ACH_U, ACH_U * 4, mb);
            bulk_cp(d + 2 * ACH_U * 4,  BHt + (size_t)cc * BCH_U, BCH_U * 4, mb);
            bulk_cp(d + 2 * ACH_U * 4 + BCH_U * 4, BLt + (size_t)cc * BCH_U, BCH_U * 4, mb);
        };

        float acc[2][4][4];
#pragma unroll
        for (int mf = 0; mf < 2; mf++)
#pragma unroll
            for (int nf = 0; nf < 4; nf++)
#pragma unroll
                for (int q = 0; q < 4; q++) acc[mf][nf][q] = 0.f;

        issue(0); issue(1); issue(2);

        for (int cch = 0; cch < NCH; cch++) {
            const int s = cch & 3;
            mbar_wait(smb + s * 8, (cch >> 2) & 1);
            const uint32_t* sAH = smu + 256 + s * STG_U;
            const uint32_t* sAL = sAH + ACH_U;
            const uint32_t* sBH = sAL + ACH_U;
            const uint32_t* sBL = sBH + BCH_U;
#pragma unroll
            for (int ks = 0; ks < 2; ks++) {
                uint4 aH0 = *(const uint4*)(sAH + ((wm_g * 2 + ks) * 2 + 0) * 128 + lid * 4);
                uint4 aH1 = *(const uint4*)(sAH + ((wm_g * 2 + ks) * 2 + 1) * 128 + lid * 4);
                uint4 aL0 = *(const uint4*)(sAL + ((wm_g * 2 + ks) * 2 + 0) * 128 + lid * 4);
                uint4 aL1 = *(const uint4*)(sAL + ((wm_g * 2 + ks) * 2 + 1) * 128 + lid * 4);
                uint4 bh0 = *(const uint4*)(sBH + (wn_g * 2 + ks) * 256 + lid * 8);
                uint4 bh1 = *(const uint4*)(sBH + (wn_g * 2 + ks) * 256 + lid * 8 + 4);
                uint4 bl0 = *(const uint4*)(sBL + (wn_g * 2 + ks) * 256 + lid * 8);
                uint4 bl1 = *(const uint4*)(sBL + (wn_g * 2 + ks) * 256 + lid * 8 + 4);
                uint32_t bHf[4][2] = {{bh0.x, bh0.y}, {bh0.z, bh0.w}, {bh1.x, bh1.y}, {bh1.z, bh1.w}};
                uint32_t bLf[4][2] = {{bl0.x, bl0.y}, {bl0.z, bl0.w}, {bl1.x, bl1.y}, {bl1.z, bl1.w}};
#pragma unroll
                for (int nf = 0; nf < 4; nf++) {
                    mma_bf16(acc[0][nf], aH0, bHf[nf][0], bHf[nf][1]);
                    mma_bf16(acc[1][nf], aH1, bHf[nf][0], bHf[nf][1]);
                }
#pragma unroll
                for (int nf = 0; nf < 4; nf++) {
                    mma_bf16(acc[0][nf], aH0, bLf[nf][0], bLf[nf][1]);
                    mma_bf16(acc[1][nf], aH1, bLf[nf][0], bLf[nf][1]);
                }
#pragma unroll
                for (int nf = 0; nf < 4; nf++) {
                    mma_bf16(acc[0][nf], aL0, bHf[nf][0], bHf[nf][1]);
                    mma_bf16(acc[1][nf], aL1, bHf[nf][0], bHf[nf][1]);
                }
            }
            __syncthreads();
            if (cch + 3 < NCH) issue(cch + 3);
        }

        // ---- fused LSTM-cell epilogue ----
        const int jb = blockIdx.x * 16 + wn_g * 8 + tig * 2;
        const int chunk = blockIdx.x >> 1;
        const int ksb   = blockIdx.x & 1;
#pragma unroll
        for (int mf = 0; mf < 2; mf++) {
            float hv[2][2];
#pragma unroll
            for (int half = 0; half < 2; half++) {
                int m = bm + wm_g * 32 + mf * 16 + half * 8 + gid;
                int tokm = isEnc ? __ldcg(&inputs[(size_t)m * T_ + step]) : __ldcg(&tok[m]);
                float* hrow = h + (size_t)m * H_ + jb;
                if (tokm != 0) {
                    const float* arow = tbl + (size_t)tokm * N4H + bn + wn_g * 32 + tig * 2;
                    float* crow = c + (size_t)m * H_ + jb;
#pragma unroll
                    for (int e = 0; e < 2; e++) {
                        int q = half * 2 + e;
                        float vi = acc[mf][0][q] + arow[e];
                        float vf = acc[mf][1][q] + arow[8 + e];
                        float vg = acc[mf][2][q] + arow[16 + e];
                        float vo = acc[mf][3][q] + arow[24 + e];
                        float c2 = sigf(vf) * crow[e] + sigf(vi) * tanhf(vg);
                        float h2 = sigf(vo) * tanhf(c2);
                        crow[e] = c2;
                        hrow[e] = h2;
                        hv[half][e] = h2;
                    }
                } else {
                    hv[half][0] = hrow[0];
                    hv[half][1] = hrow[1];
                }
            }
            uint32_t pH0, pL0, pH1, pL1;
            bsplit2(hv[0][0], hv[0][1], pH0, pL0);
            bsplit2(hv[1][0], hv[1][1], pH1, pL1);
            size_t base = ((size_t)(blockIdx.y * NCH + chunk)) * ACH_U
                        + (size_t)(((wm_g * 2 + ksb) * 2 + mf) * 128)
                        + (gid * 4 + tig) * 4 + wn_g * 2;
            uint2 vh; vh.x = pH0; vh.y = pH1;
            uint2 vl; vl.x = pL0; vl.y = pL1;
            *(uint2*)(oAH + base) = vh;
            *(uint2*)(oAL + base) = vl;
        }

        grid_bar();

        if (!isEnc) {
            // ---- inlined decoder output on 64 CTAs (4 rows each) ----
            if (linear < 64) {
                int m0 = linear * 4;
                int l  = step - T_;
                float* hs  = (float*)(smu + 256);
                float* red = hs + 4096;
                float* sc  = red + V_;
                for (int idx = tid; idx < 4096; idx += 256) {
                    int r = idx >> 10;
                    hs[idx] = __ldcg(&h[(size_t)(m0 + r) * H_ + (idx & 1023)]);
                }
                __syncthreads();
                float accv[4] = {0.f, 0.f, 0.f, 0.f};
                float bb = 0.f;
                if (tid < V_) {
                    bb = outb[tid];
#pragma unroll 8
                    for (int k = 0; k < H_; k++) {
                        float w = outW[(size_t)k * V_ + tid];
                        accv[0] += hs[k] * w;
                        accv[1] += hs[1024 + k] * w;
                        accv[2] += hs[2048 + k] * w;
                        accv[3] += hs[3072 + k] * w;
                    }
                }
                for (int r = 0; r < 4; r++) {
                    if (tid < V_) red[tid] = accv[r] + bb;
                    __syncthreads();
                    if (tid == 0) {
                        float mx = red[0]; int am = 0;
                        for (int q = 1; q < V_; q++) if (red[q] > mx) { mx = red[q]; am = q; }
                        sc[0] = mx; ((int*)sc)[2] = am;
                    }
                    __syncthreads();
                    float e = 0.f;
                    if (tid < V_) { e = expf(red[tid] - sc[0]); red[tid] = e; }
                    __syncthreads();
                    if (tid == 0) {
                        float ssum = 0.f;
                        for (int q = 0; q < V_; q++) ssum += red[q];
                        sc[1] = ssum;
                    }
                    __syncthreads();
                    int m = m0 + r;
                    if (tid < V_) out[(size_t)m * (L_ * V_) + (size_t)l * V_ + tid] = e / sc[1];
                    if (tid == 0) {
                        tok[m] = ((int*)sc)[2];
                        if (tokOut) tokOut[(size_t)l * B_ + m] = (float)((int*)sc)[2];
                    }
                    __syncthreads();
                }
            }
            grid_bar();
        }
        pb ^= 1;
    }
}

// ---------------- init ----------------
__global__ void init_state(float* __restrict__ h, float* __restrict__ c,
                           uint32_t* __restrict__ AH, uint32_t* __restrict__ AL,
                           int* __restrict__ tok, unsigned* __restrict__ barCnt)
{
    int i = blockIdx.x * blockDim.x + threadIdx.x;
    if (i < B_ * H_) { h[i] = 0.f; c[i] = 0.f; }
    if (i < B_ * H_ / 2) { AH[i] = 0u; AL[i] = 0u; }
    if (i < B_) tok[i] = V_ - 1;
    if (i == 0) *barCnt = 0;
}

// ---------------- launch ----------------
extern "C" void kernel_launch(void* const* d_in, const int* in_sizes, int n_in,
                              void* d_out, int out_size)
{
    int base = 1;
    if (n_in >= 12 && in_sizes[1] == 1) base = 2;

    const int*   inputs  = (const int*)  d_in[0];
    const float* enc_emb = (const float*)d_in[base + 0];
    const float* enc_W   = (const float*)d_in[base + 1];
    const float* enc_U   = (const float*)d_in[base + 2];
    const float* enc_b   = (const float*)d_in[base + 3];
    const float* dec_emb = (const float*)d_in[base + 4];
    const float* dec_W   = (const float*)d_in[base + 5];
    const float* dec_U   = (const float*)d_in[base + 6];
    const float* dec_b   = (const float*)d_in[base + 7];
    const float* out_W   = (const float*)d_in[base + 8];
    const float* out_b   = (const float*)d_in[base + 9];
    float* out = (float*)d_out;

    float *p_h, *p_c, *p_encEW, *p_decEW;
    uint32_t *pA0H, *pA0L, *pA1H, *pA1L, *p_EH, *p_EL, *p_BeH, *p_BeL, *p_BdH, *p_BdL, *p_BwH, *p_BwL;
    int* p_tok;
    unsigned* p_barCnt;
    cudaGetSymbolAddress((void**)&p_h, g_h);
    cudaGetSymbolAddress((void**)&p_c, g_c);
    cudaGetSymbolAddress((void**)&p_tok, g_tok);
    cudaGetSymbolAddress((void**)&pA0H, g_A0H);
    cudaGetSymbolAddress((void**)&pA0L, g_A0L);
    cudaGetSymbolAddress((void**)&pA1H, g_A1H);
    cudaGetSymbolAddress((void**)&pA1L, g_A1L);
    cudaGetSymbolAddress((void**)&p_EH, g_EH);
    cudaGetSymbolAddress((void**)&p_EL, g_EL);
    cudaGetSymbolAddress((void**)&p_BeH, g_BeH);
    cudaGetSymbolAddress((void**)&p_BeL, g_BeL);
    cudaGetSymbolAddress((void**)&p_BdH, g_BdH);
    cudaGetSymbolAddress((void**)&p_BdL, g_BdL);
    cudaGetSymbolAddress((void**)&p_BwH, g_BwH);
    cudaGetSymbolAddress((void**)&p_BwL, g_BwL);
    cudaGetSymbolAddress((void**)&p_encEW, g_encEW);
    cudaGetSymbolAddress((void**)&p_decEW, g_decEW);
    cudaGetSymbolAddress((void**)&p_barCnt, g_barCnt);

    float* tokOut = nullptr;
    if (out_size >= B_ * L_ * V_ + L_ * B_) tokOut = out + (size_t)B_ * L_ * V_;

    cudaFuncSetAttribute(gemm_table, cudaFuncAttributeMaxDynamicSharedMemorySize, SMEM_BYTES);
    cudaFuncSetAttribute(lstm_persist, cudaFuncAttributeMaxDynamicSharedMemorySize, SMEM_BYTES);

    init_state<<<(B_ * H_ + 255) / 256, 256>>>(p_h, p_c, pA0H, pA0L, p_tok, p_barCnt);

    dim3 wg(128, H_ / 32);

    // ---- table builds ----
    split_weightB<<<wg, 256>>>(enc_W, p_BwH, p_BwL);
    emb_blob<<<32, 256>>>(enc_emb, p_EH, p_EL);
    gemm_table<<<64, 256, SMEM_BYTES>>>(p_EH, p_EL, p_BwH, p_BwL, enc_b, p_encEW);
    split_weightB<<<wg, 256>>>(dec_W, p_BwH, p_BwL);
    emb_blob<<<32, 256>>>(dec_emb, p_EH, p_EL);
    gemm_table<<<64, 256, SMEM_BYTES>>>(p_EH, p_EL, p_BwH, p_BwL, dec_b, p_decEW);
    split_weightB<<<wg, 256>>>(enc_U, p_BeH, p_BeL);
    split_weightB<<<wg, 256>>>(dec_U, p_BdH, p_BdL);

    // ---- persistent fused recurrence ----
    lstm_persist<<<dim3(64, 2), 256, SMEM_BYTES>>>(
        inputs, p_BeH, p_BeL, p_BdH, p_BdL, p_encEW, p_decEW,
        p_h, p_c, p_tok, pA0H, pA0L, pA1H, pA1L,
        out_W, out_b, out, tokOut);
}

// round 15
// speedup vs baseline: 1.6266x; 1.0425x over previous
#include <cuda_runtime.h>
#include <cuda_bf16.h>
#include <math.h>
#include <stdint.h>

#define B_   256
#define T_   64
#define H_   1024
#define V_   128
#define L_   32
#define N4H  4096

#define NCH   32
#define ACH_U 2048
#define BCH_U 1024
#define NSTAGE 4
#define STG_U (2*ACH_U + 2*BCH_U)
#define STG_BYTES (STG_U * 4)
#define SMEM_BYTES (1024 + NSTAGE * STG_BYTES)
#define NCTA 128

// ---------------- persistent device scratch ----------------
__device__ float    g_h[B_ * H_];
__device__ float    g_c[B_ * H_];
__device__ int      g_tok[B_];
__device__ uint32_t g_A0H[B_ * H_ / 2];
__device__ uint32_t g_A0L[B_ * H_ / 2];
__device__ uint32_t g_A1H[B_ * H_ / 2];
__device__ uint32_t g_A1L[B_ * H_ / 2];
__device__ uint32_t g_EH[V_ * H_ / 2];
__device__ uint32_t g_EL[V_ * H_ / 2];
__device__ uint32_t g_BeH[(size_t)N4H * H_ / 2];
__device__ uint32_t g_BeL[(size_t)N4H * H_ / 2];
__device__ uint32_t g_BdH[(size_t)N4H * H_ / 2];
__device__ uint32_t g_BdL[(size_t)N4H * H_ / 2];
__device__ uint32_t g_BwH[(size_t)N4H * H_ / 2];
__device__ uint32_t g_BwL[(size_t)N4H * H_ / 2];
__device__ float    g_encEW[V_ * N4H];
__device__ float    g_decEW[V_ * N4H];
__device__ unsigned g_barCnt = 0;
__device__ volatile unsigned g_barGen = 0;

// ---------------- helpers ----------------
__device__ __forceinline__ uint32_t packb(float lo_elem, float hi_elem) {
    __nv_bfloat162 t = __floats2bfloat162_rn(lo_elem, hi_elem);
    return *(uint32_t*)&t;
}
__device__ __forceinline__ void bsplit2(float x0, float x1, uint32_t& hi, uint32_t& lo) {
    __nv_bfloat16 b0 = __float2bfloat16(x0), b1 = __float2bfloat16(x1);
    float f0 = __bfloat162float(b0), f1 = __bfloat162float(b1);
    __nv_bfloat162 th; th.x = b0; th.y = b1;
    hi = *(uint32_t*)&th;
    lo = packb(x0 - f0, x1 - f1);
}
__device__ __forceinline__ void mma_bf16(float* d, const uint4& a, uint32_t b0, uint32_t b1) {
    asm volatile(
        "mma.sync.aligned.m16n8k16.row.col.f32.bf16.bf16.f32 "
        "{%0,%1,%2,%3}, {%4,%5,%6,%7}, {%8,%9}, {%0,%1,%2,%3};"
        : "+f"(d[0]), "+f"(d[1]), "+f"(d[2]), "+f"(d[3])
        : "r"(a.x), "r"(a.y), "r"(a.z), "r"(a.w), "r"(b0), "r"(b1));
}
__device__ __forceinline__ void mbar_init(uint32_t a, uint32_t cnt) {
    asm volatile("mbarrier.init.shared.b64 [%0], %1;" :: "r"(a), "r"(cnt) : "memory");
}
__device__ __forceinline__ void mbar_expect_tx(uint32_t a, uint32_t bytes) {
    asm volatile("mbarrier.arrive.expect_tx.shared.b64 _, [%0], %1;" :: "r"(a), "r"(bytes) : "memory");
}
__device__ __forceinline__ void mbar_arrive(uint32_t a) {
    asm volatile("mbarrier.arrive.shared.b64 _, [%0];" :: "r"(a) : "memory");
}
__device__ __forceinline__ void mbar_wait(uint32_t a, uint32_t ph) {
    asm volatile(
        "{\n\t.reg .pred P;\n\t"
        "W%=:\n\t"
        "mbarrier.try_wait.parity.acquire.cta.shared::cta.b64 P, [%0], %1, 0x989680;\n\t"
        "@!P bra W%=;\n\t}"
        :: "r"(a), "r"(ph) : "memory");
}
__device__ __forceinline__ void bulk_cp(uint32_t dst, const void* src, uint32_t bytes, uint32_t mbar) {
    asm volatile(
        "cp.async.bulk.shared::cluster.global.mbarrier::complete_tx::bytes [%0], [%1], %2, [%3];"
        :: "r"(dst), "l"(src), "r"(bytes), "r"(mbar) : "memory");
}
__device__ __forceinline__ float sigf(float x) { return 1.0f / (1.0f + expf(-x)); }

__device__ __forceinline__ void grid_bar() {
    __threadfence();
    __syncthreads();
    if (threadIdx.x == 0) {
        unsigned gen = g_barGen;
        if (atomicAdd(&g_barCnt, 1u) == NCTA - 1u) {
            g_barCnt = 0;
            __threadfence();
            g_barGen = gen + 1;
        } else {
            while (g_barGen == gen) {}
        }
    }
    __syncthreads();
    __threadfence();
}

__device__ __forceinline__ void write_Ablob(uint32_t* AH, uint32_t* AL, int m, int j0,
                                            const float* r0, const float* r1)
{
    int tile = m >> 7, chunk = j0 >> 5, wm_g = (m & 127) >> 5;
    int ks = (j0 & 31) >> 4, half8 = (j0 & 15) >> 3;
    int mf = (m & 31) >> 4, gid = m & 7;
    size_t base = ((size_t)(tile * NCH + chunk)) * ACH_U + (size_t)(((wm_g * 2 + ks) * 2 + mf) * 128);
#pragma unroll
    for (int tig = 0; tig < 4; tig++) {
        int lane = gid * 4 + tig;
        uint32_t pH0, pL0, pH1, pL1;
        bsplit2(r0[2 * tig], r0[2 * tig + 1], pH0, pL0);
        bsplit2(r1[2 * tig], r1[2 * tig + 1], pH1, pL1);
        uint2 vh; vh.x = pH0; vh.y = pH1;
        uint2 vl; vl.x = pL0; vl.y = pL1;
        *(uint2*)(AH + base + lane * 4 + half8 * 2) = vh;
        *(uint2*)(AL + base + lane * 4 + half8 * 2) = vl;
    }
}

// ---------------- weight split (PERMUTED columns) ----------------
__global__ void split_weightB(const float* __restrict__ W,
                              uint32_t* __restrict__ BH, uint32_t* __restrict__ BL)
{
    __shared__ float sH[32][33];
    __shared__ float sL[32][33];
    int bx = blockIdx.x >> 1, wg = blockIdx.x & 1;
    int k0 = blockIdx.y * 32;
    int tx = threadIdx.x & 31, ty = threadIdx.x >> 5;
    int lcol = (tx >> 3) * 1024 + bx * 16 + wg * 8 + (tx & 7);
#pragma unroll
    for (int i = 0; i < 4; i++) {
        int k = ty + i * 8;
        float x = W[(size_t)(k0 + k) * N4H + lcol];
        __nv_bfloat16 bh = __float2bfloat16(x);
        float hf = __bfloat162float(bh);
        sH[k][tx] = hf;
        sL[k][tx] = __bfloat162float(__float2bfloat16(x - hf));
    }
    __syncthreads();
    int ks   = threadIdx.x >> 7;
    int lane = (threadIdx.x >> 2) & 31;
    int q    = threadIdx.x & 3;
    int gid = lane >> 2, tig = lane & 3;
    int ncol = q * 8 + gid;
    int kb = ks * 16 + 2 * tig;
    uint32_t b0H = packb(sH[kb][ncol],     sH[kb + 1][ncol]);
    uint32_t b1H = packb(sH[kb + 8][ncol], sH[kb + 9][ncol]);
    uint32_t b0L = packb(sL[kb][ncol],     sL[kb + 1][ncol]);
    uint32_t b1L = packb(sL[kb + 8][ncol], sL[kb + 9][ncol]);
    int chunk = k0 >> 5;
    size_t ob = ((size_t)(bx * NCH + chunk)) * BCH_U + wg * 512 + ks * 256 + lane * 8 + q * 2;
    uint2 vh; vh.x = b0H; vh.y = b1H;
    uint2 vl; vl.x = b0L; vl.y = b1L;
    *(uint2*)(BH + ob) = vh;
    *(uint2*)(BL + ob) = vl;
}

// ---------------- emb -> A blob ----------------
__global__ void emb_blob(const float* __restrict__ emb,
                         uint32_t* __restrict__ AH, uint32_t* __restrict__ AL)
{
    int t = blockIdx.x * 256 + threadIdx.x;
    if (t >= 8192) return;
    int mp = t >> 7;
    int m  = ((mp >> 3) << 4) | (mp & 7);
    int j0 = (t & 127) << 3;
    float r0[8], r1[8];
    const float* p0 = emb + (size_t)m * H_ + j0;
    const float* p1 = emb + (size_t)(m + 8) * H_ + j0;
#pragma unroll
    for (int i = 0; i < 8; i++) { r0[i] = p0[i]; r1[i] = p1[i]; }
    write_Ablob(AH, AL, m, j0, r0, r1);
}

// ---------------- table-build GEMM ----------------
__global__ __launch_bounds__(256)
void gemm_table(const uint32_t* __restrict__ AH, const uint32_t* __restrict__ AL,
                const uint32_t* __restrict__ BH, const uint32_t* __restrict__ BL,
                const float* __restrict__ bias, float* __restrict__ Z)
{
    extern __shared__ uint32_t smu[];
    const int tid = threadIdx.x;
    const int wid = tid >> 5;
    const int lid = tid & 31;
    const int gid = lid >> 2;
    const int tig = lid & 3;
    const int bn  = blockIdx.x * 64;
    const int wm_g = wid & 3;
    const int wn_g = wid >> 2;

    const uint32_t* BHt = BH + (size_t)blockIdx.x * NCH * BCH_U;
    const uint32_t* BLt = BL + (size_t)blockIdx.x * NCH * BCH_U;

    const uint32_t smb = (uint32_t)__cvta_generic_to_shared(smu);
    if (tid == 0) {
#pragma unroll
        for (int s = 0; s < NSTAGE; s++) mbar_init(smb + s * 8, 1);
        asm volatile("fence.proxy.async.shared::cta;" ::: "memory");
    }
    __syncthreads();

    auto issue = [&](int cc) {
        if (tid != 0) return;
        int s = cc & 3;
        uint32_t mb = smb + s * 8;
        uint32_t d  = smb + 1024 + s * STG_BYTES;
        mbar_expect_tx(mb, STG_BYTES);
        bulk_cp(d,                  AH + (size_t)cc * ACH_U, ACH_U * 4, mb);
        bulk_cp(d + ACH_U * 4,      AL + (size_t)cc * ACH_U, ACH_U * 4, mb);
        bulk_cp(d + 2 * ACH_U * 4,  BHt + (size_t)cc * BCH_U, BCH_U * 4, mb);
        bulk_cp(d + 2 * ACH_U * 4 + BCH_U * 4, BLt + (size_t)cc * BCH_U, BCH_U * 4, mb);
    };

    float acc[2][4][4];
#pragma unroll
    for (int mf = 0; mf < 2; mf++)
#pragma unroll
        for (int nf = 0; nf < 4; nf++)
#pragma unroll
            for (int q = 0; q < 4; q++) acc[mf][nf][q] = 0.f;

    issue(0); issue(1); issue(2);

    for (int cch = 0; cch < NCH; cch++) {
        const int s = cch & 3;
        mbar_wait(smb + s * 8, (cch >> 2) & 1);
        const uint32_t* sAH = smu + 256 + s * STG_U;
        const uint32_t* sAL = sAH + ACH_U;
        const uint32_t* sBH = sAL + ACH_U;
        const uint32_t* sBL = sBH + BCH_U;
#pragma unroll
        for (int ks = 0; ks < 2; ks++) {
            uint4 aH0 = *(const uint4*)(sAH + ((wm_g * 2 + ks) * 2 + 0) * 128 + lid * 4);
            uint4 aH1 = *(const uint4*)(sAH + ((wm_g * 2 + ks) * 2 + 1) * 128 + lid * 4);
            uint4 aL0 = *(const uint4*)(sAL + ((wm_g * 2 + ks) * 2 + 0) * 128 + lid * 4);
            uint4 aL1 = *(const uint4*)(sAL + ((wm_g * 2 + ks) * 2 + 1) * 128 + lid * 4);
            uint4 bh0 = *(const uint4*)(sBH + (wn_g * 2 + ks) * 256 + lid * 8);
            uint4 bh1 = *(const uint4*)(sBH + (wn_g * 2 + ks) * 256 + lid * 8 + 4);
            uint4 bl0 = *(const uint4*)(sBL + (wn_g * 2 + ks) * 256 + lid * 8);
            uint4 bl1 = *(const uint4*)(sBL + (wn_g * 2 + ks) * 256 + lid * 8 + 4);
            uint32_t bHf[4][2] = {{bh0.x, bh0.y}, {bh0.z, bh0.w}, {bh1.x, bh1.y}, {bh1.z, bh1.w}};
            uint32_t bLf[4][2] = {{bl0.x, bl0.y}, {bl0.z, bl0.w}, {bl1.x, bl1.y}, {bl1.z, bl1.w}};
#pragma unroll
            for (int nf = 0; nf < 4; nf++) {
                mma_bf16(acc[0][nf], aH0, bHf[nf][0], bHf[nf][1]);
                mma_bf16(acc[1][nf], aH1, bHf[nf][0], bHf[nf][1]);
            }
#pragma unroll
            for (int nf = 0; nf < 4; nf++) {
                mma_bf16(acc[0][nf], aH0, bLf[nf][0], bLf[nf][1]);
                mma_bf16(acc[1][nf], aH1, bLf[nf][0], bLf[nf][1]);
            }
#pragma unroll
            for (int nf = 0; nf < 4; nf++) {
                mma_bf16(acc[0][nf], aL0, bHf[nf][0], bHf[nf][1]);
                mma_bf16(acc[1][nf], aL1, bHf[nf][0], bHf[nf][1]);
            }
        }
        __syncthreads();
        if (cch + 3 < NCH) issue(cch + 3);
    }

#pragma unroll
    for (int mf = 0; mf < 2; mf++) {
#pragma unroll
        for (int half = 0; half < 2; half++) {
            int m = wm_g * 32 + mf * 16 + half * 8 + gid;
            float* zrow = Z + (size_t)m * N4H;
#pragma unroll
            for (int nf = 0; nf < 4; nf++) {
                int cn = bn + wn_g * 32 + nf * 8 + tig * 2;
                float v0 = acc[mf][nf][half * 2 + 0];
                float v1 = acc[mf][nf][half * 2 + 1];
                int lc = nf * 1024 + (bn >> 2) + wn_g * 8 + tig * 2;
                v0 += bias[lc]; v1 += bias[lc + 1];
                float2 o; o.x = v0; o.y = v1;
                *(float2*)(zrow + cn) = o;
            }
        }
    }
}

// ---------------- persistent fused kernel ----------------
__global__ __launch_bounds__(256, 1)
void lstm_persist(const int* __restrict__ inputs,
                  const uint32_t* __restrict__ BeH, const uint32_t* __restrict__ BeL,
                  const uint32_t* __restrict__ BdH, const uint32_t* __restrict__ BdL,
                  const float* __restrict__ encEW, const float* __restrict__ decEW,
                  float* __restrict__ h, float* __restrict__ c, int* __restrict__ tok,
                  uint32_t* __restrict__ A0H, uint32_t* __restrict__ A0L,
                  uint32_t* __restrict__ A1H, uint32_t* __restrict__ A1L,
                  const float* __restrict__ outW, const float* __restrict__ outb,
                  float* __restrict__ out, float* __restrict__ tokOut)
{
    extern __shared__ uint32_t smu[];
    const int tid = threadIdx.x;
    const int wid = tid >> 5;
    const int lid = tid & 31;
    const int gid = lid >> 2;
    const int tig = lid & 3;
    const int bn  = blockIdx.x * 64;
    const int bm  = blockIdx.y * 128;
    const int wm_g = wid & 3;
    const int wn_g = wid >> 2;
    const int linear = blockIdx.y * 64 + blockIdx.x;

    const uint32_t smb = (uint32_t)__cvta_generic_to_shared(smu);
    // full[s] @ smb + s*8  (count 1, tx-based); empty[s] @ smb + 32 + s*8 (count 8)
    if (tid == 0) {
#pragma unroll
        for (int s = 0; s < NSTAGE; s++) { mbar_init(smb + s * 8, 1); mbar_init(smb + 32 + s * 8, 8); }
        asm volatile("fence.proxy.async.shared::cta;" ::: "memory");
    }
    __syncthreads();

    const size_t yoff = (size_t)blockIdx.y * NCH * ACH_U;
    const size_t xoff = (size_t)blockIdx.x * NCH * BCH_U;
    int pb = 0;

    for (int step = 0; step < T_ + L_; step++) {
        const bool isEnc = step < T_;
        const uint32_t* AHt = (pb ? A1H : A0H) + yoff;
        const uint32_t* ALt = (pb ? A1L : A0L) + yoff;
        const uint32_t* BHt = (isEnc ? BeH : BdH) + xoff;
        const uint32_t* BLt = (isEnc ? BeL : BdL) + xoff;
        const float* tbl = isEnc ? encEW : decEW;
        uint32_t* oAH = (pb ? A0H : A1H);
        uint32_t* oAL = (pb ? A0L : A1L);

        auto issue = [&](int cc) {
            int s = cc & 3;
            uint32_t mb = smb + s * 8;
            uint32_t d  = smb + 1024 + s * STG_BYTES;
            mbar_expect_tx(mb, STG_BYTES);
            bulk_cp(d,                  AHt + (size_t)cc * ACH_U, ACH_U * 4, mb);
            bulk_cp(d + ACH_U * 4,      ALt + (size_t)cc * ACH_U, ACH_U * 4, mb);
            bulk_cp(d + 2 * ACH_U * 4,  BHt + (size_t)cc * BCH_U, BCH_U * 4, mb);
            bulk_cp(d + 2 * ACH_U * 4 + BCH_U * 4, BLt + (size_t)cc * BCH_U, BCH_U * 4, mb);
        };

        float acc[2][4][4];
#pragma unroll
        for (int mf = 0; mf < 2; mf++)
#pragma unroll
            for (int nf = 0; nf < 4; nf++)
#pragma unroll
                for (int q = 0; q < 4; q++) acc[mf][nf][q] = 0.f;

        if (tid == 0) { issue(0); issue(1); issue(2); }

        for (int cch = 0; cch < NCH; cch++) {
            const int s = cch & 3;
            mbar_wait(smb + s * 8, (cch >> 2) & 1);
            const uint32_t* sAH = smu + 256 + s * STG_U;
            const uint32_t* sAL = sAH + ACH_U;
            const uint32_t* sBH = sAL + ACH_U;
            const uint32_t* sBL = sBH + BCH_U;
#pragma unroll
            for (int ks = 0; ks < 2; ks++) {
                uint4 aH0 = *(const uint4*)(sAH + ((wm_g * 2 + ks) * 2 + 0) * 128 + lid * 4);
                uint4 aH1 = *(const uint4*)(sAH + ((wm_g * 2 + ks) * 2 + 1) * 128 + lid * 4);
                uint4 aL0 = *(const uint4*)(sAL + ((wm_g * 2 + ks) * 2 + 0) * 128 + lid * 4);
                uint4 aL1 = *(const uint4*)(sAL + ((wm_g * 2 + ks) * 2 + 1) * 128 + lid * 4);
                uint4 bh0 = *(const uint4*)(sBH + (wn_g * 2 + ks) * 256 + lid * 8);
                uint4 bh1 = *(const uint4*)(sBH + (wn_g * 2 + ks) * 256 + lid * 8 + 4);
                uint4 bl0 = *(const uint4*)(sBL + (wn_g * 2 + ks) * 256 + lid * 8);
                uint4 bl1 = *(const uint4*)(sBL + (wn_g * 2 + ks) * 256 + lid * 8 + 4);
                uint32_t bHf[4][2] = {{bh0.x, bh0.y}, {bh0.z, bh0.w}, {bh1.x, bh1.y}, {bh1.z, bh1.w}};
                uint32_t bLf[4][2] = {{bl0.x, bl0.y}, {bl0.z, bl0.w}, {bl1.x, bl1.y}, {bl1.z, bl1.w}};
#pragma unroll
                for (int nf = 0; nf < 4; nf++) {
                    mma_bf16(acc[0][nf], aH0, bHf[nf][0], bHf[nf][1]);
                    mma_bf16(acc[1][nf], aH1, bHf[nf][0], bHf[nf][1]);
                }
#pragma unroll
                for (int nf = 0; nf < 4; nf++) {
                    mma_bf16(acc[0][nf], aH0, bLf[nf][0], bLf[nf][1]);
                    mma_bf16(acc[1][nf], aH1, bLf[nf][0], bLf[nf][1]);
                }
#pragma unroll
                for (int nf = 0; nf < 4; nf++) {
                    mma_bf16(acc[0][nf], aL0, bHf[nf][0], bHf[nf][1]);
                    mma_bf16(acc[1][nf], aL1, bHf[nf][0], bHf[nf][1]);
                }
            }
            // fragments consumed (MMAs read regs) -> release stage
            if (lid == 0) mbar_arrive(smb + 32 + s * 8);
            if (tid == 0 && cch + 3 < NCH) {
                int c2 = cch + 3;
                if (c2 >= 4) mbar_wait(smb + 32 + (c2 & 3) * 8, ((c2 >> 2) - 1) & 1);
                issue(c2);
            }
        }

        // bar_B: for steps after a decoder output, tok must be final before epilogue
        if (step > T_) grid_bar();

        // ---- fused LSTM-cell epilogue ----
        const int jb = blockIdx.x * 16 + wn_g * 8 + tig * 2;
        const int chunk = blockIdx.x >> 1;
        const int ksb   = blockIdx.x & 1;
#pragma unroll
        for (int mf = 0; mf < 2; mf++) {
            float hv[2][2];
#pragma unroll
            for (int half = 0; half < 2; half++) {
                int m = bm + wm_g * 32 + mf * 16 + half * 8 + gid;
                int tokm = isEnc ? __ldcg(&inputs[(size_t)m * T_ + step]) : __ldcg(&tok[m]);
                float* hrow = h + (size_t)m * H_ + jb;
                if (tokm != 0) {
                    const float* arow = tbl + (size_t)tokm * N4H + bn + wn_g * 32 + tig * 2;
                    float* crow = c + (size_t)m * H_ + jb;
#pragma unroll
                    for (int e = 0; e < 2; e++) {
                        int q = half * 2 + e;
                        float vi = acc[mf][0][q] + arow[e];
                        float vf = acc[mf][1][q] + arow[8 + e];
                        float vg = acc[mf][2][q] + arow[16 + e];
                        float vo = acc[mf][3][q] + arow[24 + e];
                        float c2v = sigf(vf) * crow[e] + sigf(vi) * tanhf(vg);
                        float h2 = sigf(vo) * tanhf(c2v);
                        crow[e] = c2v;
                        hrow[e] = h2;
                        hv[half][e] = h2;
                    }
                } else {
                    hv[half][0] = hrow[0];
                    hv[half][1] = hrow[1];
                }
            }
            uint32_t pH0, pL0, pH1, pL1;
            bsplit2(hv[0][0], hv[0][1], pH0, pL0);
            bsplit2(hv[1][0], hv[1][1], pH1, pL1);
            size_t base = ((size_t)(blockIdx.y * NCH + chunk)) * ACH_U
                        + (size_t)(((wm_g * 2 + ksb) * 2 + mf) * 128)
                        + (gid * 4 + tig) * 4 + wn_g * 2;
            uint2 vh; vh.x = pH0; vh.y = pH1;
            uint2 vl; vl.x = pL0; vl.y = pL1;
            *(uint2*)(oAH + base) = vh;
            *(uint2*)(oAL + base) = vl;
        }

        grid_bar();   // bar_A: A blob + h ready

        if (!isEnc && linear < 64) {
            // ---- decoder output: 4 rows per CTA, k split over thread halves ----
            int m0 = linear * 4;
            int l  = step - T_;
            float* hs  = (float*)(smu + 256);        // 4096
            float* red = hs + 4096;                  // 1024 (partials) reused for logits/exps
            float* sc  = red + 1024;                 // smax[4], ssum[4], (int)sarg[4]
            int*   sci = (int*)(sc + 8);
            for (int idx = tid; idx < 4096; idx += 256) {
                int r = idx >> 10;
                hs[idx] = __ldcg(&h[(size_t)(m0 + r) * H_ + (idx & 1023)]);
            }
            __syncthreads();
            int v = tid & 127, part = tid >> 7;
            float accv[4] = {0.f, 0.f, 0.f, 0.f};
            int kA = part * 512, kB = kA + 512;
            for (int k = kA; k < kB; k++) {
                float w = outW[(size_t)k * V_ + v];
                accv[0] += hs[k] * w;
                accv[1] += hs[1024 + k] * w;
                accv[2] += hs[2048 + k] * w;
                accv[3] += hs[3072 + k] * w;
            }
#pragma unroll
            for (int r = 0; r < 4; r++) red[part * 512 + r * 128 + v] = accv[r];
            __syncthreads();
            float logit[4];
            if (part == 0) {
                float bb = outb[v];
#pragma unroll
                for (int r = 0; r < 4; r++) {
                    logit[r] = red[r * 128 + v] + red[512 + r * 128 + v] + bb;
                }
            }
            __syncthreads();
            if (part == 0) {
#pragma unroll
                for (int r = 0; r < 4; r++) red[r * 128 + v] = logit[r];
            }
            __syncthreads();
            if (wid == 0) {
#pragma unroll
                for (int r = 0; r < 4; r++) {
                    float bv = red[r * 128 + lid]; int bi = lid;
#pragma unroll
                    for (int o = 1; o < 4; o++) {
                        float cv = red[r * 128 + lid + o * 32];
                        if (cv > bv) { bv = cv; bi = lid + o * 32; }
                    }
#pragma unroll
                    for (int off = 16; off; off >>= 1) {
                        float ov = __shfl_down_sync(0xffffffffu, bv, off);
                        int   oi = __shfl_down_sync(0xffffffffu, bi, off);
                        if (ov > bv || (ov == bv && oi < bi)) { bv = ov; bi = oi; }
                    }
                    if (lid == 0) { sc[r] = bv; sci[r] = bi; }
                }
            }
            __syncthreads();
            float ev[4];
            if (part == 0) {
#pragma unroll
                for (int r = 0; r < 4; r++) { ev[r] = expf(logit[r] - sc[r]); red[r * 128 + v] = ev[r]; }
            }
            __syncthreads();
            if (wid == 0) {
#pragma unroll
                for (int r = 0; r < 4; r++) {
                    float sv = red[r * 128 + lid] + red[r * 128 + lid + 32]
                             + red[r * 128 + lid + 64] + red[r * 128 + lid + 96];
#pragma unroll
                    for (int off = 16; off; off >>= 1)
                        sv += __shfl_down_sync(0xffffffffu, sv, off);
                    if (lid == 0) sc[4 + r] = sv;
                }
            }
            __syncthreads();
            if (part == 0) {
#pragma unroll
                for (int r = 0; r < 4; r++) {
                    int m = m0 + r;
                    out[(size_t)m * (L_ * V_) + (size_t)l * V_ + v] = ev[r] / sc[4 + r];
                }
            }
            if (tid == 0) {
#pragma unroll
                for (int r = 0; r < 4; r++) {
                    tok[m0 + r] = sci[r];
                    if (tokOut) tokOut[(size_t)l * B_ + (m0 + r)] = (float)sci[r];
                }
            }
            __syncthreads();
        }
        pb ^= 1;
    }
}

// ---------------- init ----------------
__global__ void init_state(float* __restrict__ h, float* __restrict__ c,
                           uint32_t* __restrict__ AH, uint32_t* __restrict__ AL,
                           int* __restrict__ tok, unsigned* __restrict__ barCnt)
{
    int i = blockIdx.x * blockDim.x + threadIdx.x;
    if (i < B_ * H_) { h[i] = 0.f; c[i] = 0.f; }
    if (i < B_ * H_ / 2) { AH[i] = 0u; AL[i] = 0u; }
    if (i < B_) tok[i] = V_ - 1;
    if (i == 0) *barCnt = 0;
}

// ---------------- launch ----------------
extern "C" void kernel_launch(void* const* d_in, const int* in_sizes, int n_in,
                              void* d_out, int out_size)
{
    int base = 1;
    if (n_in >= 12 && in_sizes[1] == 1) base = 2;

    const int*   inputs  = (const int*)  d_in[0];
    const float* enc_emb = (const float*)d_in[base + 0];
    const float* enc_W   = (const float*)d_in[base + 1];
    const float* enc_U   = (const float*)d_in[base + 2];
    const float* enc_b   = (const float*)d_in[base + 3];
    const float* dec_emb = (const float*)d_in[base + 4];
    const float* dec_W   = (const float*)d_in[base + 5];
    const float* dec_U   = (const float*)d_in[base + 6];
    const float* dec_b   = (const float*)d_in[base + 7];
    const float* out_W   = (const float*)d_in[base + 8];
    const float* out_b   = (const float*)d_in[base + 9];
    float* out = (float*)d_out;

    float *p_h, *p_c, *p_encEW, *p_decEW;
    uint32_t *pA0H, *pA0L, *pA1H, *pA1L, *p_EH, *p_EL, *p_BeH, *p_BeL, *p_BdH, *p_BdL, *p_BwH, *p_BwL;
    int* p_tok;
    unsigned* p_barCnt;
    cudaGetSymbolAddress((void**)&p_h, g_h);
    cudaGetSymbolAddress((void**)&p_c, g_c);
    cudaGetSymbolAddress((void**)&p_tok, g_tok);
    cudaGetSymbolAddress((void**)&pA0H, g_A0H);
    cudaGetSymbolAddress((void**)&pA0L, g_A0L);
    cudaGetSymbolAddress((void**)&pA1H, g_A1H);
    cudaGetSymbolAddress((void**)&pA1L, g_A1L);
    cudaGetSymbolAddress((void**)&p_EH, g_EH);
    cudaGetSymbolAddress((void**)&p_EL, g_EL);
    cudaGetSymbolAddress((void**)&p_BeH, g_BeH);
    cudaGetSymbolAddress((void**)&p_BeL, g_BeL);
    cudaGetSymbolAddress((void**)&p_BdH, g_BdH);
    cudaGetSymbolAddress((void**)&p_BdL, g_BdL);
    cudaGetSymbolAddress((void**)&p_BwH, g_BwH);
    cudaGetSymbolAddress((void**)&p_BwL, g_BwL);
    cudaGetSymbolAddress((void**)&p_encEW, g_encEW);
    cudaGetSymbolAddress((void**)&p_decEW, g_decEW);
    cudaGetSymbolAddress((void**)&p_barCnt, g_barCnt);

    float* tokOut = nullptr;
    if (out_size >= B_ * L_ * V_ + L_ * B_) tokOut = out + (size_t)B_ * L_ * V_;

    cudaFuncSetAttribute(gemm_table, cudaFuncAttributeMaxDynamicSharedMemorySize, SMEM_BYTES);
    cudaFuncSetAttribute(lstm_persist, cudaFuncAttributeMaxDynamicSharedMemorySize, SMEM_BYTES);

    init_state<<<(B_ * H_ + 255) / 256, 256>>>(p_h, p_c, pA0H, pA0L, p_tok, p_barCnt);

    dim3 wg(128, H_ / 32);

    split_weightB<<<wg, 256>>>(enc_W, p_BwH, p_BwL);
    emb_blob<<<32, 256>>>(enc_emb, p_EH, p_EL);
    gemm_table<<<64, 256, SMEM_BYTES>>>(p_EH, p_EL, p_BwH, p_BwL, enc_b, p_encEW);
    split_weightB<<<wg, 256>>>(dec_W, p_BwH, p_BwL);
    emb_blob<<<32, 256>>>(dec_emb, p_EH, p_EL);
    gemm_table<<<64, 256, SMEM_BYTES>>>(p_EH, p_EL, p_BwH, p_BwL, dec_b, p_decEW);
    split_weightB<<<wg, 256>>>(enc_U, p_BeH, p_BeL);
    split_weightB<<<wg, 256>>>(dec_U, p_BdH, p_BdL);

    lstm_persist<<<dim3(64, 2), 256, SMEM_BYTES>>>(
        inputs, p_BeH, p_BeL, p_BdH, p_BdL, p_encEW, p_decEW,
        p_h, p_c, p_tok, pA0H, pA0L, pA1H, pA1L,
        out_W, out_b, out, tokOut);
}

// round 16
// speedup vs baseline: 2.0171x; 1.2401x over previous
#include <cuda_runtime.h>
#include <cuda_bf16.h>
#include <math.h>
#include <stdint.h>

#define B_   256
#define T_   64
#define H_   1024
#define V_   128
#define L_   32
#define N4H  4096

#define NCH   32            // logical K-chunk images in blobs (K=32 each)
#define ACH_U 2048
#define BCH_U 1024
#define NSTAGE 4
// persistent kernel: stage = 2 chunk images
#define PST_U (2*(2*ACH_U + 2*BCH_U))          // 12288 u32 = 49152 B
#define PST_BYTES (PST_U * 4)
#define PSMEM_BYTES (1024 + NSTAGE * PST_BYTES) // 197632
// table kernel keeps 1-chunk stages
#define TST_U (2*ACH_U + 2*BCH_U)
#define TST_BYTES (TST_U * 4)
#define TSMEM_BYTES (1024 + NSTAGE * TST_BYTES)

// ---------------- persistent device scratch ----------------
__device__ float    g_h[B_ * H_];
__device__ float    g_c[B_ * H_];
__device__ int      g_tok[B_];
__device__ uint32_t g_A0H[B_ * H_ / 2];
__device__ uint32_t g_A0L[B_ * H_ / 2];
__device__ uint32_t g_A1H[B_ * H_ / 2];
__device__ uint32_t g_A1L[B_ * H_ / 2];
__device__ uint32_t g_EH[V_ * H_ / 2];
__device__ uint32_t g_EL[V_ * H_ / 2];
__device__ uint32_t g_BeH[(size_t)N4H * H_ / 2];
__device__ uint32_t g_BeL[(size_t)N4H * H_ / 2];
__device__ uint32_t g_BdH[(size_t)N4H * H_ / 2];
__device__ uint32_t g_BdL[(size_t)N4H * H_ / 2];
__device__ uint32_t g_BwH[(size_t)N4H * H_ / 2];
__device__ uint32_t g_BwL[(size_t)N4H * H_ / 2];
__device__ float    g_encEW[V_ * N4H];
__device__ float    g_decEW[V_ * N4H];
__device__ unsigned g_barCnt2[2] = {0, 0};
__device__ volatile unsigned g_barGen2[2] = {0, 0};

// ---------------- helpers ----------------
__device__ __forceinline__ uint32_t packb(float lo_elem, float hi_elem) {
    __nv_bfloat162 t = __floats2bfloat162_rn(lo_elem, hi_elem);
    return *(uint32_t*)&t;
}
__device__ __forceinline__ void bsplit2(float x0, float x1, uint32_t& hi, uint32_t& lo) {
    __nv_bfloat16 b0 = __float2bfloat16(x0), b1 = __float2bfloat16(x1);
    float f0 = __bfloat162float(b0), f1 = __bfloat162float(b1);
    __nv_bfloat162 th; th.x = b0; th.y = b1;
    hi = *(uint32_t*)&th;
    lo = packb(x0 - f0, x1 - f1);
}
__device__ __forceinline__ void mma_bf16(float* d, const uint4& a, uint32_t b0, uint32_t b1) {
    asm volatile(
        "mma.sync.aligned.m16n8k16.row.col.f32.bf16.bf16.f32 "
        "{%0,%1,%2,%3}, {%4,%5,%6,%7}, {%8,%9}, {%0,%1,%2,%3};"
        : "+f"(d[0]), "+f"(d[1]), "+f"(d[2]), "+f"(d[3])
        : "r"(a.x), "r"(a.y), "r"(a.z), "r"(a.w), "r"(b0), "r"(b1));
}
__device__ __forceinline__ void mbar_init(uint32_t a, uint32_t cnt) {
    asm volatile("mbarrier.init.shared.b64 [%0], %1;" :: "r"(a), "r"(cnt) : "memory");
}
__device__ __forceinline__ void mbar_expect_tx(uint32_t a, uint32_t bytes) {
    asm volatile("mbarrier.arrive.expect_tx.shared.b64 _, [%0], %1;" :: "r"(a), "r"(bytes) : "memory");
}
__device__ __forceinline__ void mbar_arrive(uint32_t a) {
    asm volatile("mbarrier.arrive.shared.b64 _, [%0];" :: "r"(a) : "memory");
}
__device__ __forceinline__ void mbar_wait(uint32_t a, uint32_t ph) {
    asm volatile(
        "{\n\t.reg .pred P;\n\t"
        "W%=:\n\t"
        "mbarrier.try_wait.parity.acquire.cta.shared::cta.b64 P, [%0], %1, 0x989680;\n\t"
        "@!P bra W%=;\n\t}"
        :: "r"(a), "r"(ph) : "memory");
}
__device__ __forceinline__ void bulk_cp(uint32_t dst, const void* src, uint32_t bytes, uint32_t mbar) {
    asm volatile(
        "cp.async.bulk.shared::cluster.global.mbarrier::complete_tx::bytes [%0], [%1], %2, [%3];"
        :: "r"(dst), "l"(src), "r"(bytes), "r"(mbar) : "memory");
}
__device__ __forceinline__ float sigf(float x) { return 1.0f / (1.0f + expf(-x)); }

// per-half grid barrier (64 CTAs)
__device__ __forceinline__ void grid_bar_y(int y) {
    __threadfence();
    __syncthreads();
    if (threadIdx.x == 0) {
        unsigned gen = g_barGen2[y];
        if (atomicAdd(&g_barCnt2[y], 1u) == 63u) {
            g_barCnt2[y] = 0;
            __threadfence();
            g_barGen2[y] = gen + 1;
        } else {
            while (g_barGen2[y] == gen) {}
        }
    }
    __syncthreads();
    __threadfence();
}

__device__ __forceinline__ void write_Ablob(uint32_t* AH, uint32_t* AL, int m, int j0,
                                            const float* r0, const float* r1)
{
    int tile = m >> 7, chunk = j0 >> 5, wm_g = (m & 127) >> 5;
    int ks = (j0 & 31) >> 4, half8 = (j0 & 15) >> 3;
    int mf = (m & 31) >> 4, gid = m & 7;
    size_t base = ((size_t)(tile * NCH + chunk)) * ACH_U + (size_t)(((wm_g * 2 + ks) * 2 + mf) * 128);
#pragma unroll
    for (int tig = 0; tig < 4; tig++) {
        int lane = gid * 4 + tig;
        uint32_t pH0, pL0, pH1, pL1;
        bsplit2(r0[2 * tig], r0[2 * tig + 1], pH0, pL0);
        bsplit2(r1[2 * tig], r1[2 * tig + 1], pH1, pL1);
        uint2 vh; vh.x = pH0; vh.y = pH1;
        uint2 vl; vl.x = pL0; vl.y = pL1;
        *(uint2*)(AH + base + lane * 4 + half8 * 2) = vh;
        *(uint2*)(AL + base + lane * 4 + half8 * 2) = vl;
    }
}

// ---------------- weight split (PERMUTED columns) ----------------
__global__ void split_weightB(const float* __restrict__ W,
                              uint32_t* __restrict__ BH, uint32_t* __restrict__ BL)
{
    __shared__ float sH[32][33];
    __shared__ float sL[32][33];
    int bx = blockIdx.x >> 1, wg = blockIdx.x & 1;
    int k0 = blockIdx.y * 32;
    int tx = threadIdx.x & 31, ty = threadIdx.x >> 5;
    int lcol = (tx >> 3) * 1024 + bx * 16 + wg * 8 + (tx & 7);
#pragma unroll
    for (int i = 0; i < 4; i++) {
        int k = ty + i * 8;
        float x = W[(size_t)(k0 + k) * N4H + lcol];
        __nv_bfloat16 bh = __float2bfloat16(x);
        float hf = __bfloat162float(bh);
        sH[k][tx] = hf;
        sL[k][tx] = __bfloat162float(__float2bfloat16(x - hf));
    }
    __syncthreads();
    int ks   = threadIdx.x >> 7;
    int lane = (threadIdx.x >> 2) & 31;
    int q    = threadIdx.x & 3;
    int gid = lane >> 2, tig = lane & 3;
    int ncol = q * 8 + gid;
    int kb = ks * 16 + 2 * tig;
    uint32_t b0H = packb(sH[kb][ncol],     sH[kb + 1][ncol]);
    uint32_t b1H = packb(sH[kb + 8][ncol], sH[kb + 9][ncol]);
    uint32_t b0L = packb(sL[kb][ncol],     sL[kb + 1][ncol]);
    uint32_t b1L = packb(sL[kb + 8][ncol], sL[kb + 9][ncol]);
    int chunk = k0 >> 5;
    size_t ob = ((size_t)(bx * NCH + chunk)) * BCH_U + wg * 512 + ks * 256 + lane * 8 + q * 2;
    uint2 vh; vh.x = b0H; vh.y = b1H;
    uint2 vl; vl.x = b0L; vl.y = b1L;
    *(uint2*)(BH + ob) = vh;
    *(uint2*)(BL + ob) = vl;
}

// ---------------- emb -> A blob ----------------
__global__ void emb_blob(const float* __restrict__ emb,
                         uint32_t* __restrict__ AH, uint32_t* __restrict__ AL)
{
    int t = blockIdx.x * 256 + threadIdx.x;
    if (t >= 8192) return;
    int mp = t >> 7;
    int m  = ((mp >> 3) << 4) | (mp & 7);
    int j0 = (t & 127) << 3;
    float r0[8], r1[8];
    const float* p0 = emb + (size_t)m * H_ + j0;
    const float* p1 = emb + (size_t)(m + 8) * H_ + j0;
#pragma unroll
    for (int i = 0; i < 8; i++) { r0[i] = p0[i]; r1[i] = p1[i]; }
    write_Ablob(AH, AL, m, j0, r0, r1);
}

// ---------------- table-build GEMM (1-chunk stages) ----------------
__global__ __launch_bounds__(256)
void gemm_table(const uint32_t* __restrict__ AH, const uint32_t* __restrict__ AL,
                const uint32_t* __restrict__ BH, const uint32_t* __restrict__ BL,
                const float* __restrict__ bias, float* __restrict__ Z)
{
    extern __shared__ uint32_t smu[];
    const int tid = threadIdx.x;
    const int wid = tid >> 5;
    const int lid = tid & 31;
    const int gid = lid >> 2;
    const int tig = lid & 3;
    const int bn  = blockIdx.x * 64;
    const int wm_g = wid & 3;
    const int wn_g = wid >> 2;

    const uint32_t* BHt = BH + (size_t)blockIdx.x * NCH * BCH_U;
    const uint32_t* BLt = BL + (size_t)blockIdx.x * NCH * BCH_U;

    const uint32_t smb = (uint32_t)__cvta_generic_to_shared(smu);
    if (tid == 0) {
#pragma unroll
        for (int s = 0; s < NSTAGE; s++) mbar_init(smb + s * 8, 1);
        asm volatile("fence.proxy.async.shared::cta;" ::: "memory");
    }
    __syncthreads();

    auto issue = [&](int cc) {
        if (tid != 0) return;
        int s = cc & 3;
        uint32_t mb = smb + s * 8;
        uint32_t d  = smb + 1024 + s * TST_BYTES;
        mbar_expect_tx(mb, TST_BYTES);
        bulk_cp(d,                  AH + (size_t)cc * ACH_U, ACH_U * 4, mb);
        bulk_cp(d + ACH_U * 4,      AL + (size_t)cc * ACH_U, ACH_U * 4, mb);
        bulk_cp(d + 2 * ACH_U * 4,  BHt + (size_t)cc * BCH_U, BCH_U * 4, mb);
        bulk_cp(d + 2 * ACH_U * 4 + BCH_U * 4, BLt + (size_t)cc * BCH_U, BCH_U * 4, mb);
    };

    float acc[2][4][4];
#pragma unroll
    for (int mf = 0; mf < 2; mf++)
#pragma unroll
        for (int nf = 0; nf < 4; nf++)
#pragma unroll
            for (int q = 0; q < 4; q++) acc[mf][nf][q] = 0.f;

    issue(0); issue(1); issue(2);

    for (int cch = 0; cch < NCH; cch++) {
        const int s = cch & 3;
        mbar_wait(smb + s * 8, (cch >> 2) & 1);
        const uint32_t* sAH = smu + 256 + s * TST_U;
        const uint32_t* sAL = sAH + ACH_U;
        const uint32_t* sBH = sAL + ACH_U;
        const uint32_t* sBL = sBH + BCH_U;
#pragma unroll
        for (int ks = 0; ks < 2; ks++) {
            uint4 aH0 = *(const uint4*)(sAH + ((wm_g * 2 + ks) * 2 + 0) * 128 + lid * 4);
            uint4 aH1 = *(const uint4*)(sAH + ((wm_g * 2 + ks) * 2 + 1) * 128 + lid * 4);
            uint4 aL0 = *(const uint4*)(sAL + ((wm_g * 2 + ks) * 2 + 0) * 128 + lid * 4);
            uint4 aL1 = *(const uint4*)(sAL + ((wm_g * 2 + ks) * 2 + 1) * 128 + lid * 4);
            uint4 bh0 = *(const uint4*)(sBH + (wn_g * 2 + ks) * 256 + lid * 8);
            uint4 bh1 = *(const uint4*)(sBH + (wn_g * 2 + ks) * 256 + lid * 8 + 4);
            uint4 bl0 = *(const uint4*)(sBL + (wn_g * 2 + ks) * 256 + lid * 8);
            uint4 bl1 = *(const uint4*)(sBL + (wn_g * 2 + ks) * 256 + lid * 8 + 4);
            uint32_t bHf[4][2] = {{bh0.x, bh0.y}, {bh0.z, bh0.w}, {bh1.x, bh1.y}, {bh1.z, bh1.w}};
            uint32_t bLf[4][2] = {{bl0.x, bl0.y}, {bl0.z, bl0.w}, {bl1.x, bl1.y}, {bl1.z, bl1.w}};
#pragma unroll
            for (int nf = 0; nf < 4; nf++) {
                mma_bf16(acc[0][nf], aH0, bHf[nf][0], bHf[nf][1]);
                mma_bf16(acc[1][nf], aH1, bHf[nf][0], bHf[nf][1]);
            }
#pragma unroll
            for (int nf = 0; nf < 4; nf++) {
                mma_bf16(acc[0][nf], aH0, bLf[nf][0], bLf[nf][1]);
                mma_bf16(acc[1][nf], aH1, bLf[nf][0], bLf[nf][1]);
            }
#pragma unroll
            for (int nf = 0; nf < 4; nf++) {
                mma_bf16(acc[0][nf], aL0, bHf[nf][0], bHf[nf][1]);
                mma_bf16(acc[1][nf], aL1, bHf[nf][0], bHf[nf][1]);
            }
        }
        __syncthreads();
        if (cch + 3 < NCH) issue(cch + 3);
    }

#pragma unroll
    for (int mf = 0; mf < 2; mf++) {
#pragma unroll
        for (int half = 0; half < 2; half++) {
            int m = wm_g * 32 + mf * 16 + half * 8 + gid;
            float* zrow = Z + (size_t)m * N4H;
#pragma unroll
            for (int nf = 0; nf < 4; nf++) {
                int cn = bn + wn_g * 32 + nf * 8 + tig * 2;
                float v0 = acc[mf][nf][half * 2 + 0];
                float v1 = acc[mf][nf][half * 2 + 1];
                int lc = nf * 1024 + (bn >> 2) + wn_g * 8 + tig * 2;
                v0 += bias[lc]; v1 += bias[lc + 1];
                float2 o; o.x = v0; o.y = v1;
                *(float2*)(zrow + cn) = o;
            }
        }
    }
}

// ---------------- persistent fused kernel (2-chunk stages, per-half barriers) ----------------
__global__ __launch_bounds__(256, 1)
void lstm_persist(const int* __restrict__ inputs,
                  const uint32_t* __restrict__ BeH, const uint32_t* __restrict__ BeL,
                  const uint32_t* __restrict__ BdH, const uint32_t* __restrict__ BdL,
                  const float* __restrict__ encEW, const float* __restrict__ decEW,
                  float* __restrict__ h, float* __restrict__ c, int* __restrict__ tok,
                  uint32_t* __restrict__ A0H, uint32_t* __restrict__ A0L,
                  uint32_t* __restrict__ A1H, uint32_t* __restrict__ A1L,
                  const float* __restrict__ outW, const float* __restrict__ outb,
                  float* __restrict__ out, float* __restrict__ tokOut)
{
    extern __shared__ uint32_t smu[];
    const int tid = threadIdx.x;
    const int wid = tid >> 5;
    const int lid = tid & 31;
    const int gid = lid >> 2;
    const int tig = lid & 3;
    const int bn  = blockIdx.x * 64;
    const int bm  = blockIdx.y * 128;
    const int wm_g = wid & 3;
    const int wn_g = wid >> 2;
    const int yb = blockIdx.y;
    const int linear = blockIdx.y * 64 + blockIdx.x;

    const uint32_t smb = (uint32_t)__cvta_generic_to_shared(smu);
    if (tid == 0) {
#pragma unroll
        for (int s = 0; s < NSTAGE; s++) { mbar_init(smb + s * 8, 1); mbar_init(smb + 32 + s * 8, 8); }
        asm volatile("fence.proxy.async.shared::cta;" ::: "memory");
    }
    __syncthreads();

    const size_t yoff = (size_t)blockIdx.y * NCH * ACH_U;
    const size_t xoff = (size_t)blockIdx.x * NCH * BCH_U;
    int pb = 0;

    for (int step = 0; step < T_ + L_; step++) {
        const bool isEnc = step < T_;
        const uint32_t* AHt = (pb ? A1H : A0H) + yoff;
        const uint32_t* ALt = (pb ? A1L : A0L) + yoff;
        const uint32_t* BHt = (isEnc ? BeH : BdH) + xoff;
        const uint32_t* BLt = (isEnc ? BeL : BdL) + xoff;
        const float* tbl = isEnc ? encEW : decEW;
        uint32_t* oAH = (pb ? A0H : A1H);
        uint32_t* oAL = (pb ? A0L : A1L);

        auto issue = [&](int st) {
            int s = st & 3;
            uint32_t mb = smb + s * 8;
            uint32_t d  = smb + 1024 + s * PST_BYTES;
            mbar_expect_tx(mb, PST_BYTES);
            bulk_cp(d,                      AHt + (size_t)(st * 2) * ACH_U, 2 * ACH_U * 4, mb);
            bulk_cp(d + 2 * ACH_U * 4,      ALt + (size_t)(st * 2) * ACH_U, 2 * ACH_U * 4, mb);
            bulk_cp(d + 4 * ACH_U * 4,      BHt + (size_t)(st * 2) * BCH_U, 2 * BCH_U * 4, mb);
            bulk_cp(d + (4 * ACH_U + 2 * BCH_U) * 4, BLt + (size_t)(st * 2) * BCH_U, 2 * BCH_U * 4, mb);
        };

        float acc[2][4][4];
#pragma unroll
        for (int mf = 0; mf < 2; mf++)
#pragma unroll
            for (int nf = 0; nf < 4; nf++)
#pragma unroll
                for (int q = 0; q < 4; q++) acc[mf][nf][q] = 0.f;

        if (tid == 0) { issue(0); issue(1); issue(2); }

        for (int st = 0; st < 16; st++) {
            const int s = st & 3;
            mbar_wait(smb + s * 8, (st >> 2) & 1);
            const uint32_t* stg = smu + 256 + s * PST_U;
#pragma unroll
            for (int u = 0; u < 2; u++) {
                const uint32_t* sAH = stg + u * ACH_U;
                const uint32_t* sAL = stg + 2 * ACH_U + u * ACH_U;
                const uint32_t* sBH = stg + 4 * ACH_U + u * BCH_U;
                const uint32_t* sBL = stg + 4 * ACH_U + 2 * BCH_U + u * BCH_U;
#pragma unroll
                for (int ks = 0; ks < 2; ks++) {
                    uint4 aH0 = *(const uint4*)(sAH + ((wm_g * 2 + ks) * 2 + 0) * 128 + lid * 4);
                    uint4 aH1 = *(const uint4*)(sAH + ((wm_g * 2 + ks) * 2 + 1) * 128 + lid * 4);
                    uint4 aL0 = *(const uint4*)(sAL + ((wm_g * 2 + ks) * 2 + 0) * 128 + lid * 4);
                    uint4 aL1 = *(const uint4*)(sAL + ((wm_g * 2 + ks) * 2 + 1) * 128 + lid * 4);
                    uint4 bh0 = *(const uint4*)(sBH + (wn_g * 2 + ks) * 256 + lid * 8);
                    uint4 bh1 = *(const uint4*)(sBH + (wn_g * 2 + ks) * 256 + lid * 8 + 4);
                    uint4 bl0 = *(const uint4*)(sBL + (wn_g * 2 + ks) * 256 + lid * 8);
                    uint4 bl1 = *(const uint4*)(sBL + (wn_g * 2 + ks) * 256 + lid * 8 + 4);
                    uint32_t bHf[4][2] = {{bh0.x, bh0.y}, {bh0.z, bh0.w}, {bh1.x, bh1.y}, {bh1.z, bh1.w}};
                    uint32_t bLf[4][2] = {{bl0.x, bl0.y}, {bl0.z, bl0.w}, {bl1.x, bl1.y}, {bl1.z, bl1.w}};
#pragma unroll
                    for (int nf = 0; nf < 4; nf++) {
                        mma_bf16(acc[0][nf], aH0, bHf[nf][0], bHf[nf][1]);
                        mma_bf16(acc[1][nf], aH1, bHf[nf][0], bHf[nf][1]);
                    }
#pragma unroll
                    for (int nf = 0; nf < 4; nf++) {
                        mma_bf16(acc[0][nf], aH0, bLf[nf][0], bLf[nf][1]);
                        mma_bf16(acc[1][nf], aH1, bLf[nf][0], bLf[nf][1]);
                    }
#pragma unroll
                    for (int nf = 0; nf < 4; nf++) {
                        mma_bf16(acc[0][nf], aL0, bHf[nf][0], bHf[nf][1]);
                        mma_bf16(acc[1][nf], aL1, bHf[nf][0], bHf[nf][1]);
                    }
                }
            }
            if (lid == 0) mbar_arrive(smb + 32 + s * 8);
            if (tid == 0 && st + 3 < 16) {
                int s2 = st + 3;
                if (s2 >= 4) mbar_wait(smb + 32 + (s2 & 3) * 8, ((s2 >> 2) - 1) & 1);
                issue(s2);
            }
        }

        if (step > T_) grid_bar_y(yb);   // tok final before epilogue (same half)

        // ---- fused LSTM-cell epilogue ----
        const int jb = blockIdx.x * 16 + wn_g * 8 + tig * 2;
        const int chunk = blockIdx.x >> 1;
        const int ksb   = blockIdx.x & 1;
#pragma unroll
        for (int mf = 0; mf < 2; mf++) {
            float hv[2][2];
#pragma unroll
            for (int half = 0; half < 2; half++) {
                int m = bm + wm_g * 32 + mf * 16 + half * 8 + gid;
                int tokm = isEnc ? __ldcg(&inputs[(size_t)m * T_ + step]) : __ldcg(&tok[m]);
                float* hrow = h + (size_t)m * H_ + jb;
                if (tokm != 0) {
                    const float* arow = tbl + (size_t)tokm * N4H + bn + wn_g * 32 + tig * 2;
                    float* crow = c + (size_t)m * H_ + jb;
#pragma unroll
                    for (int e = 0; e < 2; e++) {
                        int q = half * 2 + e;
                        float vi = acc[mf][0][q] + arow[e];
                        float vf = acc[mf][1][q] + arow[8 + e];
                        float vg = acc[mf][2][q] + arow[16 + e];
                        float vo = acc[mf][3][q] + arow[24 + e];
                        float c2v = sigf(vf) * crow[e] + sigf(vi) * tanhf(vg);
                        float h2 = sigf(vo) * tanhf(c2v);
                        crow[e] = c2v;
                        hrow[e] = h2;
                        hv[half][e] = h2;
                    }
                } else {
                    hv[half][0] = hrow[0];
                    hv[half][1] = hrow[1];
                }
            }
            uint32_t pH0, pL0, pH1, pL1;
            bsplit2(hv[0][0], hv[0][1], pH0, pL0);
            bsplit2(hv[1][0], hv[1][1], pH1, pL1);
            size_t base = ((size_t)(blockIdx.y * NCH + chunk)) * ACH_U
                        + (size_t)(((wm_g * 2 + ksb) * 2 + mf) * 128)
                        + (gid * 4 + tig) * 4 + wn_g * 2;
            uint2 vh; vh.x = pH0; vh.y = pH1;
            uint2 vl; vl.x = pL0; vl.y = pL1;
            *(uint2*)(oAH + base) = vh;
            *(uint2*)(oAL + base) = vl;
        }

        grid_bar_y(yb);   // A blob + h ready (within half)

        if (!isEnc) {
            // ---- decoder output: 2 rows per CTA, 128 CTAs, k split over thread halves ----
            int m0 = linear * 2;
            int l  = step - T_;
            float* hs  = (float*)(smu + 256);        // 2048
            float* red = hs + 2048;                  // 512
            float* sc  = red + 512;                  // smax[2], ssum[2]
            int*   sci = (int*)(sc + 4);             // sarg[2]
            for (int idx = tid; idx < 2048; idx += 256) {
                int r = idx >> 10;
                hs[idx] = __ldcg(&h[(size_t)(m0 + r) * H_ + (idx & 1023)]);
            }
            __syncthreads();
            int v = tid & 127, part = tid >> 7;
            float accv[2] = {0.f, 0.f};
            int kA = part * 512;
            for (int k = kA; k < kA + 512; k++) {
                float w = outW[(size_t)k * V_ + v];
                accv[0] += hs[k] * w;
                accv[1] += hs[1024 + k] * w;
            }
            red[part * 256 + v]       = accv[0];
            red[part * 256 + 128 + v] = accv[1];
            __syncthreads();
            float logit[2];
            if (part == 0) {
                float bb = outb[v];
#pragma unroll
                for (int r = 0; r < 2; r++)
                    logit[r] = red[r * 128 + v] + red[256 + r * 128 + v] + bb;
            }
            __syncthreads();
            if (part == 0) {
#pragma unroll
                for (int r = 0; r < 2; r++) red[r * 128 + v] = logit[r];
            }
            __syncthreads();
            if (wid == 0) {
#pragma unroll
                for (int r = 0; r < 2; r++) {
                    float bv = red[r * 128 + lid]; int bi = lid;
#pragma unroll
                    for (int o = 1; o < 4; o++) {
                        float cv = red[r * 128 + lid + o * 32];
                        if (cv > bv) { bv = cv; bi = lid + o * 32; }
                    }
#pragma unroll
                    for (int off = 16; off; off >>= 1) {
                        float ov = __shfl_down_sync(0xffffffffu, bv, off);
                        int   oi = __shfl_down_sync(0xffffffffu, bi, off);
                        if (ov > bv || (ov == bv && oi < bi)) { bv = ov; bi = oi; }
                    }
                    if (lid == 0) { sc[r] = bv; sci[r] = bi; }
                }
            }
            __syncthreads();
            float ev[2];
            if (part == 0) {
#pragma unroll
                for (int r = 0; r < 2; r++) { ev[r] = expf(logit[r] - sc[r]); red[r * 128 + v] = ev[r]; }
            }
            __syncthreads();
            if (wid == 0) {
#pragma unroll
                for (int r = 0; r < 2; r++) {
                    float sv = red[r * 128 + lid] + red[r * 128 + lid + 32]
                             + red[r * 128 + lid + 64] + red[r * 128 + lid + 96];
#pragma unroll
                    for (int off = 16; off; off >>= 1)
                        sv += __shfl_down_sync(0xffffffffu, sv, off);
                    if (lid == 0) sc[2 + r] = sv;
                }
            }
            __syncthreads();
            if (part == 0) {
#pragma unroll
                for (int r = 0; r < 2; r++) {
                    int m = m0 + r;
                    out[(size_t)m * (L_ * V_) + (size_t)l * V_ + v] = ev[r] / sc[2 + r];
                }
            }
            if (tid == 0) {
#pragma unroll
                for (int r = 0; r < 2; r++) {
                    tok[m0 + r] = sci[r];
                    if (tokOut) tokOut[(size_t)l * B_ + (m0 + r)] = (float)sci[r];
                }
            }
            __syncthreads();
        }
        pb ^= 1;
    }
}

// ---------------- init ----------------
__global__ void init_state(float* __restrict__ h, float* __restrict__ c,
                           uint32_t* __restrict__ AH, uint32_t* __restrict__ AL,
                           int* __restrict__ tok, unsigned* __restrict__ barCnt2)
{
    int i = blockIdx.x * blockDim.x + threadIdx.x;
    if (i < B_ * H_) { h[i] = 0.f; c[i] = 0.f; }
    if (i < B_ * H_ / 2) { AH[i] = 0u; AL[i] = 0u; }
    if (i < B_) tok[i] = V_ - 1;
    if (i < 2) barCnt2[i] = 0;
}

// ---------------- launch ----------------
extern "C" void kernel_launch(void* const* d_in, const int* in_sizes, int n_in,
                              void* d_out, int out_size)
{
    int base = 1;
    if (n_in >= 12 && in_sizes[1] == 1) base = 2;

    const int*   inputs  = (const int*)  d_in[0];
    const float* enc_emb = (const float*)d_in[base + 0];
    const float* enc_W   = (const float*)d_in[base + 1];
    const float* enc_U   = (const float*)d_in[base + 2];
    const float* enc_b   = (const float*)d_in[base + 3];
    const float* dec_emb = (const float*)d_in[base + 4];
    const float* dec_W   = (const float*)d_in[base + 5];
    const float* dec_U   = (const float*)d_in[base + 6];
    const float* dec_b   = (const float*)d_in[base + 7];
    const float* out_W   = (const float*)d_in[base + 8];
    const float* out_b   = (const float*)d_in[base + 9];
    float* out = (float*)d_out;

    float *p_h, *p_c, *p_encEW, *p_decEW;
    uint32_t *pA0H, *pA0L, *pA1H, *pA1L, *p_EH, *p_EL, *p_BeH, *p_BeL, *p_BdH, *p_BdL, *p_BwH, *p_BwL;
    int* p_tok;
    unsigned* p_barCnt2;
    cudaGetSymbolAddress((void**)&p_h, g_h);
    cudaGetSymbolAddress((void**)&p_c, g_c);
    cudaGetSymbolAddress((void**)&p_tok, g_tok);
    cudaGetSymbolAddress((void**)&pA0H, g_A0H);
    cudaGetSymbolAddress((void**)&pA0L, g_A0L);
    cudaGetSymbolAddress((void**)&pA1H, g_A1H);
    cudaGetSymbolAddress((void**)&pA1L, g_A1L);
    cudaGetSymbolAddress((void**)&p_EH, g_EH);
    cudaGetSymbolAddress((void**)&p_EL, g_EL);
    cudaGetSymbolAddress((void**)&p_BeH, g_BeH);
    cudaGetSymbolAddress((void**)&p_BeL, g_BeL);
    cudaGetSymbolAddress((void**)&p_BdH, g_BdH);
    cudaGetSymbolAddress((void**)&p_BdL, g_BdL);
    cudaGetSymbolAddress((void**)&p_BwH, g_BwH);
    cudaGetSymbolAddress((void**)&p_BwL, g_BwL);
    cudaGetSymbolAddress((void**)&p_encEW, g_encEW);
    cudaGetSymbolAddress((void**)&p_decEW, g_decEW);
    cudaGetSymbolAddress((void**)&p_barCnt2, g_barCnt2);

    float* tokOut = nullptr;
    if (out_size >= B_ * L_ * V_ + L_ * B_) tokOut = out + (size_t)B_ * L_ * V_;

    cudaFuncSetAttribute(gemm_table, cudaFuncAttributeMaxDynamicSharedMemorySize, TSMEM_BYTES);
    cudaFuncSetAttribute(lstm_persist, cudaFuncAttributeMaxDynamicSharedMemorySize, PSMEM_BYTES);

    init_state<<<(B_ * H_ + 255) / 256, 256>>>(p_h, p_c, pA0H, pA0L, p_tok, p_barCnt2);

    dim3 wg(128, H_ / 32);

    split_weightB<<<wg, 256>>>(enc_W, p_BwH, p_BwL);
    emb_blob<<<32, 256>>>(enc_emb, p_EH, p_EL);
    gemm_table<<<64, 256, TSMEM_BYTES>>>(p_EH, p_EL, p_BwH, p_BwL, enc_b, p_encEW);
    split_weightB<<<wg, 256>>>(dec_W, p_BwH, p_BwL);
    emb_blob<<<32, 256>>>(dec_emb, p_EH, p_EL);
    gemm_table<<<64, 256, TSMEM_BYTES>>>(p_EH, p_EL, p_BwH, p_BwL, dec_b, p_decEW);
    split_weightB<<<wg, 256>>>(enc_U, p_BeH, p_BeL);
    split_weightB<<<wg, 256>>>(dec_U, p_BdH, p_BdL);

    lstm_persist<<<dim3(64, 2), 256, PSMEM_BYTES>>>(
        inputs, p_BeH, p_BeL, p_BdH, p_BdL, p_encEW, p_decEW,
        p_h, p_c, p_tok, pA0H, pA0L, pA1H, pA1L,
        out_W, out_b, out, tokOut);
}